// round 5
// baseline (speedup 1.0000x reference)
#include <cuda_runtime.h>
#include <math.h>

// Problem constants
#define BB 8
#define DD 4096
#define NPROJ 12288      // 3*D
#define SS 16
#define FFD 16384
#define FIR_OFF 32768            // d_out offset of new_fir  (B*D elems of x first)
#define IIR_OFF 229376           // 32768 + 196608

typedef unsigned long long ull;

// ---------------- scratch (__device__ globals; no allocation allowed) -------
__device__ float g_xn1 [BB*DD];
__device__ float g_y   [BB*DD];
__device__ float g_xnew[BB*DD];
__device__ float g_xn2 [BB*DD];
__device__ float g_g   [BB*FFD];
__device__ float g_ssq [BB];
__device__ float g_pA  [4194304];   // split-K partials (16 MB)
__device__ float g_pB  [4194304];
__device__ float g_pC  [1048576];   // stage-1 reduced partials
__device__ float g_pD  [1048576];

__device__ __forceinline__ void fma2(ull& a, ull w, ull x) {
    asm("fma.rn.f32x2 %0, %1, %2, %0;" : "+l"(a) : "l"(w), "l"(x));
}
__device__ __forceinline__ void cp_async16(void* sdst, const void* gsrc) {
    unsigned s = (unsigned)__cvta_generic_to_shared(sdst);
    asm volatile("cp.async.cg.shared.global [%0], [%1], 16;" :: "r"(s), "l"(gsrc));
}
__device__ __forceinline__ void cp_commit() {
    asm volatile("cp.async.commit_group;");
}
template<int N> __device__ __forceinline__ void cp_wait() {
    asm volatile("cp.async.wait_group %0;" :: "n"(N));
}

// ---------------- rmsnorm of input x ----------------------------------------
__global__ void rmsnorm1_kernel(const float* __restrict__ x,
                                const float* __restrict__ w,
                                float* __restrict__ out) {
    int b = blockIdx.x;          // 8 blocks
    int tid = threadIdx.x;       // 512 threads
    float v[8];
    float ss = 0.f;
#pragma unroll
    for (int e = 0; e < 8; e++) {
        float t = x[b*DD + e*512 + tid];
        v[e] = t; ss += t*t;
    }
    __shared__ float red[16];
    int lane = tid & 31, wid = tid >> 5;
#pragma unroll
    for (int o = 16; o; o >>= 1) ss += __shfl_xor_sync(0xffffffffu, ss, o);
    if (lane == 0) red[wid] = ss;
    __syncthreads();
    if (tid == 0) { float t = 0.f; for (int i = 0; i < 16; i++) t += red[i]; red[0] = t; }
    __syncthreads();
    float scale = rsqrtf(red[0] * (1.f/DD) + 1e-6f);
#pragma unroll
    for (int e = 0; e < 8; e++)
        out[b*DD + e*512 + tid] = v[e] * scale * w[e*512 + tid];
}

// ---------------- split-K GEMV: 3-buffer x 4-row cp.async ring, occ=3 -------
// P[chunk][b][n] = sum_{k in chunk} X[b][k] * W[k][n]
// smem: 8*KCH float2 (xs2) + 3*4*256 ulonglong2 (48 KB weight ring)
template<int KCH>
__global__ __launch_bounds__(256, 3)
void gemv_partial(const float* __restrict__ W,
                  const float* __restrict__ X,
                  float* __restrict__ P, int K, int N) {
    extern __shared__ char smem[];
    float2*     xs2  = reinterpret_cast<float2*>(smem);                 // 8*KCH
    ulonglong2* wbuf = reinterpret_cast<ulonglong2*>(smem + 8*KCH*8);   // 3*1024

    int tid = threadIdx.x;               // 256 threads
    int k0  = blockIdx.y * KCH;
#pragma unroll
    for (int i = tid; i < 8*KCH; i += 256) {
        int b = i / KCH, k = i % KCH;
        float v = X[b*K + k0 + k];
        xs2[i] = make_float2(v, v);
    }
    __syncthreads();

    int Nv = N >> 2;                     // float4 columns
    int col4 = blockIdx.x*256 + tid;
    const float4* Wv = reinterpret_cast<const float4*>(W) + (size_t)k0*Nv + col4;

    // prologue: 3 stages of 4 rows each
#pragma unroll
    for (int s = 0; s < 3; s++) {
#pragma unroll
        for (int i = 0; i < 4; i++)
            cp_async16(&wbuf[(s*4 + i)*256 + tid], Wv + (size_t)(s*4+i)*Nv);
        cp_commit();
    }

    ull acc[8][2];
#pragma unroll
    for (int b = 0; b < 8; b++) { acc[b][0] = 0ull; acc[b][1] = 0ull; }

    const int nst = KCH / 4;
    int bi = 0;
#pragma unroll 1
    for (int s = 0; s < nst; s++) {
        int rem = nst - 1 - s;
        if (rem >= 2)      cp_wait<2>();
        else if (rem == 1) cp_wait<1>();
        else               cp_wait<0>();

        const ulonglong2* ws = wbuf + bi*1024 + tid;
        int kb = s*4;
#pragma unroll
        for (int i = 0; i < 4; i++) {
            ulonglong2 wv = ws[i*256];
#pragma unroll
            for (int b = 0; b < 8; b++) {
                ull xx = *reinterpret_cast<const ull*>(&xs2[b*KCH + kb + i]);
                fma2(acc[b][0], wv.x, xx);
                fma2(acc[b][1], wv.y, xx);
            }
        }
        if (s + 3 < nst) {
            const float4* src = Wv + (size_t)(s+3)*4*Nv;
#pragma unroll
            for (int i = 0; i < 4; i++)
                cp_async16(&wbuf[(bi*4 + i)*256 + tid], src + (size_t)i*Nv);
            cp_commit();
        }
        bi = (bi == 2) ? 0 : bi + 1;
    }

    ulonglong2* Pv = reinterpret_cast<ulonglong2*>(P)
                   + (size_t)blockIdx.y*(N<<1) + col4;
#pragma unroll
    for (int b = 0; b < 8; b++)
        Pv[(size_t)b*Nv] = make_ulonglong2(acc[b][0], acc[b][1]);
}

// ---------------- stage-1 chunk reduction: O[g][j] = sum_{c in group g} P[c][j]
template<int CPG>
__global__ void reduce1_kernel(const float4* __restrict__ P4,
                               float4* __restrict__ O4, int elems4) {
    int idx = blockIdx.x*256 + threadIdx.x;
    int g = blockIdx.y;
    const float4* p = P4 + (size_t)g*CPG*elems4 + idx;
    float4 v = make_float4(0,0,0,0);
#pragma unroll
    for (int c = 0; c < CPG; c++) {
        float4 t = p[(size_t)c*elems4];
        v.x += t.x; v.y += t.y; v.z += t.z; v.w += t.w;
    }
    O4[(size_t)g*elems4 + idx] = v;
}

template<int CPG>
__global__ void reduce1_pair_kernel(const float4* __restrict__ PA4,
                                    const float4* __restrict__ PB4,
                                    float4* __restrict__ OA4,
                                    float4* __restrict__ OB4, int elems4) {
    int idx = blockIdx.x*256 + threadIdx.x;
    int g = blockIdx.y;
    const float4* pa = PA4 + (size_t)g*CPG*elems4 + idx;
    const float4* pb = PB4 + (size_t)g*CPG*elems4 + idx;
    float4 va = make_float4(0,0,0,0), vb = make_float4(0,0,0,0);
#pragma unroll
    for (int c = 0; c < CPG; c++) {
        float4 ta = pa[(size_t)c*elems4];
        float4 tb = pb[(size_t)c*elems4];
        va.x += ta.x; va.y += ta.y; va.z += ta.z; va.w += ta.w;
        vb.x += tb.x; vb.y += tb.y; vb.z += tb.z; vb.w += tb.w;
    }
    OA4[(size_t)g*elems4 + idx] = va;
    OB4[(size_t)g*elems4 + idx] = vb;
}

// ---------------- FIR + gating split + IIR (reads 4 pre-reduced chunks) -----
__global__ void fir_iir_kernel(const float* __restrict__ P,
                               const float* __restrict__ fir_state,
                               const float* __restrict__ sfw,
                               const float* __restrict__ sfb,
                               const float* __restrict__ iir,
                               const float* __restrict__ lp,
                               const float* __restrict__ resid,
                               const float* __restrict__ Dres,
                               float* __restrict__ y,
                               float* __restrict__ dout) {
    int blk = blockIdx.x;                // 256 blocks = 8 batch * 32 heads
    int b = blk >> 5, h = blk & 31;
    int j = threadIdx.x;                 // 128 threads = DPH
    if (blk == 0 && j < BB) g_ssq[j] = 0.f;   // pre-zero for reduce_res

    float zp[3];
#pragma unroll
    for (int e = 0; e < 3; e++) {
        int i  = h*384 + e*128 + j;
        int gi = b*NPROJ + i;
        float u = 0.f;
#pragma unroll
        for (int c = 0; c < 4; c++) u += P[c*(8*NPROJ) + gi];
        float f0 = fir_state[gi*2 + 0];
        float f1 = fir_state[gi*2 + 1];
        float w0 = sfw[i*3 + 0], w1 = sfw[i*3 + 1], w2 = sfw[i*3 + 2];
        zp[e] = w2*u + f0*w0 + f1*w1 + sfb[i];
        dout[FIR_OFF + gi*2 + 0] = f1;   // new_fir = [f1, u]
        dout[FIR_OFF + gi*2 + 1] = u;
    }
    int d = h*128 + j;
    float x2 = zp[0], x1 = zp[1], v = zp[2];
    float x1v = x1 * v;
    float res = 0.f;
    int base = (b*DD + d)*SS;
#pragma unroll
    for (int s = 0; s < SS; s++) {
        float pole = expf(lp[d*SS + s]);
        float ni = fmaf(pole, iir[base + s], x1v);
        dout[IIR_OFF + base + s] = ni;
        res = fmaf(resid[d*SS + s], ni, res);
    }
    y[b*DD + d] = x2 * (res + Dres[d]*x1v);
}

// ---------------- reduce out_w (8 pre-reduced) + bias + residual + ssq ------
__global__ void reduce_res_kernel(const float4* __restrict__ P4,
                                  const float4* __restrict__ x4,
                                  const float4* __restrict__ ob4,
                                  float4* __restrict__ xnew4) {
    int g4 = blockIdx.x*128 + threadIdx.x;    // 8192 float4 total, 64 blocks
    int b = g4 >> 10, n4 = g4 & 1023;
    float4 v = x4[g4], o = ob4[n4];
    v.x += o.x; v.y += o.y; v.z += o.z; v.w += o.w;
#pragma unroll
    for (int c = 0; c < 8; c++) {
        float4 p = P4[c*8192 + g4];
        v.x += p.x; v.y += p.y; v.z += p.z; v.w += p.w;
    }
    xnew4[g4] = v;
    float ss = v.x*v.x + v.y*v.y + v.z*v.z + v.w*v.w;
#pragma unroll
    for (int o2 = 16; o2; o2 >>= 1) ss += __shfl_xor_sync(0xffffffffu, ss, o2);
    __shared__ float red[4];
    int lane = threadIdx.x & 31, wid = threadIdx.x >> 5;
    if (lane == 0) red[wid] = ss;
    __syncthreads();
    if (threadIdx.x == 0) {
        float t = red[0] + red[1] + red[2] + red[3];
        atomicAdd(&g_ssq[b], t);
    }
}

// ---------------- post-norm scale -------------------------------------------
__global__ void scale_kernel(const float* __restrict__ xnew,
                             const float* __restrict__ w,
                             float* __restrict__ xn2) {
    int gid = blockIdx.x*256 + threadIdx.x;
    int b = gid >> 12, n = gid & (DD-1);
    xn2[gid] = xnew[gid] * rsqrtf(g_ssq[b]*(1.f/DD) + 1e-6f) * w[n];
}

// ---------------- SwiGLU: g = silu(sum pC) * (sum pD)  (4 chunks each) ------
__global__ void glu_kernel(const float4* __restrict__ PA4,
                           const float4* __restrict__ PB4,
                           float4* __restrict__ g4out) {
    int g4 = blockIdx.x*256 + threadIdx.x;    // 32768 float4, 128 blocks
    float4 a = make_float4(0,0,0,0), c3 = make_float4(0,0,0,0);
#pragma unroll
    for (int c = 0; c < 4; c++) {
        float4 pa = PA4[c*32768 + g4];
        float4 pb = PB4[c*32768 + g4];
        a.x += pa.x; a.y += pa.y; a.z += pa.z; a.w += pa.w;
        c3.x += pb.x; c3.y += pb.y; c3.z += pb.z; c3.w += pb.w;
    }
    float4 r;
    r.x = (a.x / (1.f + expf(-a.x))) * c3.x;
    r.y = (a.y / (1.f + expf(-a.y))) * c3.y;
    r.z = (a.z / (1.f + expf(-a.z))) * c3.z;
    r.w = (a.w / (1.f + expf(-a.w))) * c3.w;
    g4out[g4] = r;
}

// ---------------- final: x_out = xnew + reduce8(pre-reduced) -----------------
__global__ void final_kernel(const float4* __restrict__ P4,
                             const float4* __restrict__ xnew4,
                             float4* __restrict__ dout4) {
    int g4 = blockIdx.x*128 + threadIdx.x;    // 8192 float4, 64 blocks
    float4 v = xnew4[g4];
#pragma unroll
    for (int c = 0; c < 8; c++) {
        float4 p = P4[c*8192 + g4];
        v.x += p.x; v.y += p.y; v.z += p.z; v.w += p.w;
    }
    dout4[g4] = v;
}

// ---------------- host launcher ----------------------------------------------
extern "C" void kernel_launch(void* const* d_in, const int* in_sizes, int n_in,
                              void* d_out, int out_size) {
    (void)in_sizes; (void)n_in; (void)out_size;
    const float* x          = (const float*)d_in[0];
    const float* fir_state  = (const float*)d_in[1];
    const float* iir_state  = (const float*)d_in[2];
    const float* pre_w      = (const float*)d_in[3];
    const float* proj_w     = (const float*)d_in[4];
    const float* sfw        = (const float*)d_in[5];
    const float* sfb        = (const float*)d_in[6];
    const float* Dres       = (const float*)d_in[7];
    const float* resid      = (const float*)d_in[8];
    const float* lp         = (const float*)d_in[9];
    const float* out_w      = (const float*)d_in[10];
    const float* out_b      = (const float*)d_in[11];
    const float* post_w     = (const float*)d_in[12];
    const float* w1         = (const float*)d_in[13];
    const float* w3         = (const float*)d_in[14];
    const float* w2         = (const float*)d_in[15];
    float* out = (float*)d_out;

    float *xn1, *y, *xnew, *xn2, *g, *pA, *pB, *pC, *pD;
    cudaGetSymbolAddress((void**)&xn1,  g_xn1);
    cudaGetSymbolAddress((void**)&y,    g_y);
    cudaGetSymbolAddress((void**)&xnew, g_xnew);
    cudaGetSymbolAddress((void**)&xn2,  g_xn2);
    cudaGetSymbolAddress((void**)&g,    g_g);
    cudaGetSymbolAddress((void**)&pA,   g_pA);
    cudaGetSymbolAddress((void**)&pB,   g_pB);
    cudaGetSymbolAddress((void**)&pC,   g_pC);
    cudaGetSymbolAddress((void**)&pD,   g_pD);

    // dynamic smem: xs2 (8*KCH*8 B) + 3-stage weight ring (49152 B)
    const int smem64  = 8*64*8  + 49152;   // 53248
    const int smem128 = 8*128*8 + 49152;   // 57344
    const int smem256 = 8*256*8 + 49152;   // 65536
    cudaFuncSetAttribute(gemv_partial<64>,
                         cudaFuncAttributeMaxDynamicSharedMemorySize, smem64);
    cudaFuncSetAttribute(gemv_partial<128>,
                         cudaFuncAttributeMaxDynamicSharedMemorySize, smem128);
    cudaFuncSetAttribute(gemv_partial<256>,
                         cudaFuncAttributeMaxDynamicSharedMemorySize, smem256);

    // 1. pre-norm
    rmsnorm1_kernel<<<BB, 512>>>(x, pre_w, xn1);
    // 2. z = xn1 @ proj_w (4096x12288): 12 col x 32 chunks = 384 blocks
    gemv_partial<128><<<dim3(12,32), 256, smem128>>>(proj_w, xn1, pA, DD, NPROJ);
    // 3. stage-1 reduce: 32 -> 4 chunks  (elems4 = 8*12288/4 = 24576)
    reduce1_kernel<8><<<dim3(96,4), 256>>>((const float4*)pA, (float4*)pC, 24576);
    // 4. FIR + split + IIR -> y, new_fir, new_iir (also zeroes g_ssq)
    fir_iir_kernel<<<256, 128>>>(pC, fir_state, sfw, sfb, iir_state, lp, resid, Dres, y, out);
    // 5. y @ out_w (4096x4096): 4 col x 64 chunks = 256 blocks
    gemv_partial<64><<<dim3(4,64), 256, smem64>>>(out_w, y, pA, DD, DD);
    // 6. stage-1 reduce: 64 -> 8 chunks (elems4 = 8192)
    reduce1_kernel<8><<<dim3(32,8), 256>>>((const float4*)pA, (float4*)pC, 8192);
    // 7. xnew = reduce8 + out_b + x; accumulate sum of squares
    reduce_res_kernel<<<64, 128>>>((const float4*)pC, (const float4*)x,
                                   (const float4*)out_b, (float4*)xnew);
    // 8. xn2 = rmsnorm(xnew) * post_w
    scale_kernel<<<128, 256>>>(xnew, post_w, xn2);
    // 9/10. MLP up (4096x16384): 16 col x 32 chunks = 512 blocks each
    gemv_partial<128><<<dim3(16,32), 256, smem128>>>(w1, xn2, pA, DD, FFD);
    gemv_partial<128><<<dim3(16,32), 256, smem128>>>(w3, xn2, pB, DD, FFD);
    // 11. stage-1 reduce both: 32 -> 4 chunks (elems4 = 32768)
    reduce1_pair_kernel<8><<<dim3(128,4), 256>>>((const float4*)pA, (const float4*)pB,
                                                 (float4*)pC, (float4*)pD, 32768);
    // 12. SwiGLU gate
    glu_kernel<<<128, 256>>>((const float4*)pC, (const float4*)pD, (float4*)g);
    // 13. g @ mlp_w2 (16384x4096): 4 col x 64 chunks = 256 blocks
    gemv_partial<256><<<dim3(4,64), 256, smem256>>>(w2, g, pA, FFD, DD);
    // 14. stage-1 reduce: 64 -> 8 chunks (elems4 = 8192)
    reduce1_kernel<8><<<dim3(32,8), 256>>>((const float4*)pA, (float4*)pC, 8192);
    // 15. x_out = xnew + reduce8
    final_kernel<<<64, 128>>>((const float4*)pC, (const float4*)xnew, (float4*)out);
}

// round 6
// speedup vs baseline: 1.2230x; 1.2230x over previous
#include <cuda_runtime.h>
#include <math.h>

// Problem constants
#define BB 8
#define DD 4096
#define NPROJ 12288      // 3*D
#define SS 16
#define FFD 16384
#define FIR_OFF 32768            // d_out offset of new_fir  (B*D elems of x first)
#define IIR_OFF 229376           // 32768 + 196608

typedef unsigned long long ull;

// ---------------- scratch (__device__ globals; no allocation allowed) -------
__device__ float g_xn1 [BB*DD];
__device__ float g_y   [BB*DD];
__device__ float g_xnew[BB*DD];
__device__ float g_xn2 [BB*DD];
__device__ float g_g   [BB*FFD];
__device__ float g_ssq [BB];
__device__ float g_pA  [4194304];   // split-K partials
__device__ float g_pB  [4194304];

__device__ __forceinline__ void fma2(ull& a, ull w, ull x) {
    asm("fma.rn.f32x2 %0, %1, %2, %0;" : "+l"(a) : "l"(w), "l"(x));
}
__device__ __forceinline__ void cp_async16(void* sdst, const void* gsrc) {
    unsigned s = (unsigned)__cvta_generic_to_shared(sdst);
    asm volatile("cp.async.cg.shared.global [%0], [%1], 16;" :: "r"(s), "l"(gsrc));
}
__device__ __forceinline__ void cp_commit() {
    asm volatile("cp.async.commit_group;");
}
template<int N> __device__ __forceinline__ void cp_wait() {
    asm volatile("cp.async.wait_group %0;" :: "n"(N));
}

// ---------------- rmsnorm of input x ----------------------------------------
__global__ void rmsnorm1_kernel(const float* __restrict__ x,
                                const float* __restrict__ w,
                                float* __restrict__ out) {
    int b = blockIdx.x;          // 8 blocks
    int tid = threadIdx.x;       // 512 threads
    float v[8];
    float ss = 0.f;
#pragma unroll
    for (int e = 0; e < 8; e++) {
        float t = x[b*DD + e*512 + tid];
        v[e] = t; ss += t*t;
    }
    __shared__ float red[16];
    int lane = tid & 31, wid = tid >> 5;
#pragma unroll
    for (int o = 16; o; o >>= 1) ss += __shfl_xor_sync(0xffffffffu, ss, o);
    if (lane == 0) red[wid] = ss;
    __syncthreads();
    if (tid == 0) { float t = 0.f; for (int i = 0; i < 16; i++) t += red[i]; red[0] = t; }
    __syncthreads();
    float scale = rsqrtf(red[0] * (1.f/DD) + 1e-6f);
#pragma unroll
    for (int e = 0; e < 8; e++)
        out[b*DD + e*512 + tid] = v[e] * scale * w[e*512 + tid];
}

// ---------------- split-K GEMV: cp.async double-buffered smem staging -------
// (identical structure to the proven R4 kernel; occ=2, 8-row stages)
template<int KCH>
__global__ __launch_bounds__(256, 2)
void gemv_partial(const float* __restrict__ W,
                  const float* __restrict__ X,
                  float* __restrict__ P, int K, int N) {
    extern __shared__ char smem[];
    float2*     xs2  = reinterpret_cast<float2*>(smem);                 // 8*KCH
    ulonglong2* wbuf = reinterpret_cast<ulonglong2*>(smem + 8*KCH*8);   // 2*8*256

    int tid = threadIdx.x;               // 256 threads
    int k0  = blockIdx.y * KCH;
#pragma unroll
    for (int i = tid; i < 8*KCH; i += 256) {
        int b = i / KCH, k = i % KCH;
        float v = X[b*K + k0 + k];
        xs2[i] = make_float2(v, v);
    }
    __syncthreads();

    int Nv = N >> 2;                     // float4 columns
    int col4 = blockIdx.x*256 + tid;
    const float4* Wv = reinterpret_cast<const float4*>(W) + (size_t)k0*Nv + col4;

#pragma unroll
    for (int i = 0; i < 8; i++)
        cp_async16(&wbuf[(0*8 + i)*256 + tid], Wv + (size_t)i*Nv);
    cp_commit();
#pragma unroll
    for (int i = 0; i < 8; i++)
        cp_async16(&wbuf[(1*8 + i)*256 + tid], Wv + (size_t)(8+i)*Nv);
    cp_commit();

    ull acc[8][2];
#pragma unroll
    for (int b = 0; b < 8; b++) { acc[b][0] = 0ull; acc[b][1] = 0ull; }

    const int nstages = KCH / 8;
#pragma unroll 1
    for (int s = 0; s < nstages; s++) {
        if (s + 1 < nstages) cp_wait<1>(); else cp_wait<0>();
        int sb = s & 1;
        const ulonglong2* ws = wbuf + sb*2048 + tid;
        int kb = s*8;
#pragma unroll
        for (int i = 0; i < 8; i++) {
            ulonglong2 wv = ws[i*256];
#pragma unroll
            for (int b = 0; b < 8; b++) {
                ull xx = *reinterpret_cast<const ull*>(&xs2[b*KCH + kb + i]);
                fma2(acc[b][0], wv.x, xx);
                fma2(acc[b][1], wv.y, xx);
            }
        }
        if (s + 2 < nstages) {
            const float4* src = Wv + (size_t)(s+2)*8*Nv;
#pragma unroll
            for (int i = 0; i < 8; i++)
                cp_async16(&wbuf[(sb*8 + i)*256 + tid], src + (size_t)i*Nv);
            cp_commit();
        }
    }

    ulonglong2* Pv = reinterpret_cast<ulonglong2*>(P)
                   + (size_t)blockIdx.y*(N<<1) + col4;
#pragma unroll
    for (int b = 0; b < 8; b++)
        Pv[(size_t)b*Nv] = make_ulonglong2(acc[b][0], acc[b][1]);
}

// ---------------- dual GEMV for w1/w3 (blockIdx.z selects matrix) ------------
template<int KCH>
__global__ __launch_bounds__(256, 2)
void gemv_dual(const float* __restrict__ W1,
               const float* __restrict__ W3,
               const float* __restrict__ X,
               float* __restrict__ P1,
               float* __restrict__ P3, int K, int N) {
    extern __shared__ char smem[];
    float2*     xs2  = reinterpret_cast<float2*>(smem);
    ulonglong2* wbuf = reinterpret_cast<ulonglong2*>(smem + 8*KCH*8);

    const float* W = blockIdx.z ? W3 : W1;
    float*       P = blockIdx.z ? P3 : P1;

    int tid = threadIdx.x;
    int k0  = blockIdx.y * KCH;
#pragma unroll
    for (int i = tid; i < 8*KCH; i += 256) {
        int b = i / KCH, k = i % KCH;
        float v = X[b*K + k0 + k];
        xs2[i] = make_float2(v, v);
    }
    __syncthreads();

    int Nv = N >> 2;
    int col4 = blockIdx.x*256 + tid;
    const float4* Wv = reinterpret_cast<const float4*>(W) + (size_t)k0*Nv + col4;

#pragma unroll
    for (int i = 0; i < 8; i++)
        cp_async16(&wbuf[(0*8 + i)*256 + tid], Wv + (size_t)i*Nv);
    cp_commit();
#pragma unroll
    for (int i = 0; i < 8; i++)
        cp_async16(&wbuf[(1*8 + i)*256 + tid], Wv + (size_t)(8+i)*Nv);
    cp_commit();

    ull acc[8][2];
#pragma unroll
    for (int b = 0; b < 8; b++) { acc[b][0] = 0ull; acc[b][1] = 0ull; }

    const int nstages = KCH / 8;
#pragma unroll 1
    for (int s = 0; s < nstages; s++) {
        if (s + 1 < nstages) cp_wait<1>(); else cp_wait<0>();
        int sb = s & 1;
        const ulonglong2* ws = wbuf + sb*2048 + tid;
        int kb = s*8;
#pragma unroll
        for (int i = 0; i < 8; i++) {
            ulonglong2 wv = ws[i*256];
#pragma unroll
            for (int b = 0; b < 8; b++) {
                ull xx = *reinterpret_cast<const ull*>(&xs2[b*KCH + kb + i]);
                fma2(acc[b][0], wv.x, xx);
                fma2(acc[b][1], wv.y, xx);
            }
        }
        if (s + 2 < nstages) {
            const float4* src = Wv + (size_t)(s+2)*8*Nv;
#pragma unroll
            for (int i = 0; i < 8; i++)
                cp_async16(&wbuf[(sb*8 + i)*256 + tid], src + (size_t)i*Nv);
            cp_commit();
        }
    }

    ulonglong2* Pv = reinterpret_cast<ulonglong2*>(P)
                   + (size_t)blockIdx.y*(N<<1) + col4;
#pragma unroll
    for (int b = 0; b < 8; b++)
        Pv[(size_t)b*Nv] = make_ulonglong2(acc[b][0], acc[b][1]);
}

// ---------------- FIR + gating split + IIR (384 threads: 3 parallel gates) --
__global__ void fir_iir_kernel(const float* __restrict__ P,
                               const float* __restrict__ fir_state,
                               const float* __restrict__ sfw,
                               const float* __restrict__ sfb,
                               const float* __restrict__ iir,
                               const float* __restrict__ lp,
                               const float* __restrict__ resid,
                               const float* __restrict__ Dres,
                               float* __restrict__ y,
                               float* __restrict__ dout) {
    __shared__ float zps[384];
    int blk = blockIdx.x;                // 256 blocks = 8 batch * 32 heads
    int b = blk >> 5, h = blk & 31;
    int tid = threadIdx.x;               // 384 threads
    int e = tid >> 7, j = tid & 127;
    if (blk == 0 && tid < BB) g_ssq[tid] = 0.f;   // pre-zero for reduce_res

    {
        int i  = h*384 + e*128 + j;
        int gi = b*NPROJ + i;
        float u = 0.f;
#pragma unroll
        for (int c = 0; c < 16; c++) u += P[c*(8*NPROJ) + gi];
        float f0 = fir_state[gi*2 + 0];
        float f1 = fir_state[gi*2 + 1];
        float w0 = sfw[i*3 + 0], w1 = sfw[i*3 + 1], w2 = sfw[i*3 + 2];
        zps[tid] = w2*u + f0*w0 + f1*w1 + sfb[i];
        dout[FIR_OFF + gi*2 + 0] = f1;   // new_fir = [f1, u]
        dout[FIR_OFF + gi*2 + 1] = u;
    }
    __syncthreads();
    if (tid < 128) {
        int d = h*128 + tid;
        float x2 = zps[tid], x1 = zps[128+tid], v = zps[256+tid];
        float x1v = x1 * v;
        float res = 0.f;
        int base = (b*DD + d)*SS;
#pragma unroll
        for (int s = 0; s < SS; s++) {
            float pole = __expf(lp[d*SS + s]);
            float ni = fmaf(pole, iir[base + s], x1v);
            dout[IIR_OFF + base + s] = ni;
            res = fmaf(resid[d*SS + s], ni, res);
        }
        y[b*DD + d] = x2 * (res + Dres[d]*x1v);
    }
}

// ---------------- reduce out_w (64 chunks, 8-way split) + bias + res + ssq --
__global__ void reduce_res_kernel(const float4* __restrict__ P4,
                                  const float4* __restrict__ x4,
                                  const float4* __restrict__ ob4,
                                  float4* __restrict__ xnew4) {
    __shared__ float4 sp[8][32];
    int tid = threadIdx.x;               // 256: j = tid&31 element, sub = tid>>5
    int j = tid & 31, sub = tid >> 5;
    int e = blockIdx.x*32 + j;           // 256 blocks -> 8192 float4
    float4 v = make_float4(0,0,0,0);
#pragma unroll
    for (int i = 0; i < 8; i++) {
        float4 t = P4[(size_t)(sub*8 + i)*8192 + e];
        v.x += t.x; v.y += t.y; v.z += t.z; v.w += t.w;
    }
    sp[sub][j] = v;
    __syncthreads();
    if (sub == 0) {
        int b = e >> 10;
        float4 o = ob4[e & 1023];
        float4 r = x4[e];
        r.x += o.x; r.y += o.y; r.z += o.z; r.w += o.w;
#pragma unroll
        for (int s = 0; s < 8; s++) {
            float4 t = sp[s][j];
            r.x += t.x; r.y += t.y; r.z += t.z; r.w += t.w;
        }
        xnew4[e] = r;
        float ss = r.x*r.x + r.y*r.y + r.z*r.z + r.w*r.w;
#pragma unroll
        for (int o2 = 16; o2; o2 >>= 1) ss += __shfl_xor_sync(0xffffffffu, ss, o2);
        if (j == 0) atomicAdd(&g_ssq[b], ss);
    }
}

// ---------------- post-norm scale -------------------------------------------
__global__ void scale_kernel(const float* __restrict__ xnew,
                             const float* __restrict__ w,
                             float* __restrict__ xn2) {
    int gid = blockIdx.x*256 + threadIdx.x;
    int b = gid >> 12, n = gid & (DD-1);
    xn2[gid] = xnew[gid] * rsqrtf(g_ssq[b]*(1.f/DD) + 1e-6f) * w[n];
}

// ---------------- SwiGLU (16 chunks each, 4-way split) -----------------------
__global__ void glu_kernel(const float4* __restrict__ PA4,
                           const float4* __restrict__ PB4,
                           float4* __restrict__ g4out) {
    __shared__ float4 sa[4][64], sb[4][64];
    int tid = threadIdx.x;               // 256: j = tid&63, sub = tid>>6
    int j = tid & 63, sub = tid >> 6;
    int e = blockIdx.x*64 + j;           // 512 blocks -> 32768 float4
    float4 a = make_float4(0,0,0,0), c3 = make_float4(0,0,0,0);
#pragma unroll
    for (int i = 0; i < 4; i++) {
        float4 pa = PA4[(size_t)(sub*4 + i)*32768 + e];
        float4 pb = PB4[(size_t)(sub*4 + i)*32768 + e];
        a.x += pa.x; a.y += pa.y; a.z += pa.z; a.w += pa.w;
        c3.x += pb.x; c3.y += pb.y; c3.z += pb.z; c3.w += pb.w;
    }
    sa[sub][j] = a; sb[sub][j] = c3;
    __syncthreads();
    if (sub == 0) {
        float4 ra = make_float4(0,0,0,0), rb = make_float4(0,0,0,0);
#pragma unroll
        for (int s = 0; s < 4; s++) {
            float4 ta = sa[s][j], tb = sb[s][j];
            ra.x += ta.x; ra.y += ta.y; ra.z += ta.z; ra.w += ta.w;
            rb.x += tb.x; rb.y += tb.y; rb.z += tb.z; rb.w += tb.w;
        }
        float4 r;
        r.x = (ra.x / (1.f + __expf(-ra.x))) * rb.x;
        r.y = (ra.y / (1.f + __expf(-ra.y))) * rb.y;
        r.z = (ra.z / (1.f + __expf(-ra.z))) * rb.z;
        r.w = (ra.w / (1.f + __expf(-ra.w))) * rb.w;
        g4out[e] = r;
    }
}

// ---------------- final: x_out = xnew + reduce64 (8-way split) ---------------
__global__ void final_kernel(const float4* __restrict__ P4,
                             const float4* __restrict__ xnew4,
                             float4* __restrict__ dout4) {
    __shared__ float4 sp[8][32];
    int tid = threadIdx.x;
    int j = tid & 31, sub = tid >> 5;
    int e = blockIdx.x*32 + j;           // 256 blocks -> 8192 float4
    float4 v = make_float4(0,0,0,0);
#pragma unroll
    for (int i = 0; i < 8; i++) {
        float4 t = P4[(size_t)(sub*8 + i)*8192 + e];
        v.x += t.x; v.y += t.y; v.z += t.z; v.w += t.w;
    }
    sp[sub][j] = v;
    __syncthreads();
    if (sub == 0) {
        float4 r = xnew4[e];
#pragma unroll
        for (int s = 0; s < 8; s++) {
            float4 t = sp[s][j];
            r.x += t.x; r.y += t.y; r.z += t.z; r.w += t.w;
        }
        dout4[e] = r;
    }
}

// ---------------- host launcher ----------------------------------------------
extern "C" void kernel_launch(void* const* d_in, const int* in_sizes, int n_in,
                              void* d_out, int out_size) {
    (void)in_sizes; (void)n_in; (void)out_size;
    const float* x          = (const float*)d_in[0];
    const float* fir_state  = (const float*)d_in[1];
    const float* iir_state  = (const float*)d_in[2];
    const float* pre_w      = (const float*)d_in[3];
    const float* proj_w     = (const float*)d_in[4];
    const float* sfw        = (const float*)d_in[5];
    const float* sfb        = (const float*)d_in[6];
    const float* Dres       = (const float*)d_in[7];
    const float* resid      = (const float*)d_in[8];
    const float* lp         = (const float*)d_in[9];
    const float* out_w      = (const float*)d_in[10];
    const float* out_b      = (const float*)d_in[11];
    const float* post_w     = (const float*)d_in[12];
    const float* w1         = (const float*)d_in[13];
    const float* w3         = (const float*)d_in[14];
    const float* w2         = (const float*)d_in[15];
    float* out = (float*)d_out;

    float *xn1, *y, *xnew, *xn2, *g, *pA, *pB;
    cudaGetSymbolAddress((void**)&xn1,  g_xn1);
    cudaGetSymbolAddress((void**)&y,    g_y);
    cudaGetSymbolAddress((void**)&xnew, g_xnew);
    cudaGetSymbolAddress((void**)&xn2,  g_xn2);
    cudaGetSymbolAddress((void**)&g,    g_g);
    cudaGetSymbolAddress((void**)&pA,   g_pA);
    cudaGetSymbolAddress((void**)&pB,   g_pB);

    // dynamic smem: xs2 (8*KCH*8 B) + weight stages (65536 B)
    const int smem256 = 8*256*8 + 65536;   // 81920
    const int smem64  = 8*64*8  + 65536;   // 69632
    cudaFuncSetAttribute(gemv_partial<256>,
                         cudaFuncAttributeMaxDynamicSharedMemorySize, smem256);
    cudaFuncSetAttribute(gemv_partial<64>,
                         cudaFuncAttributeMaxDynamicSharedMemorySize, smem64);
    cudaFuncSetAttribute(gemv_dual<256>,
                         cudaFuncAttributeMaxDynamicSharedMemorySize, smem256);

    // 1. pre-norm
    rmsnorm1_kernel<<<BB, 512>>>(x, pre_w, xn1);
    // 2. z = xn1 @ proj_w (4096x12288): 12 col x 16 chunks = 192 blocks
    gemv_partial<256><<<dim3(12,16), 256, smem256>>>(proj_w, xn1, pA, DD, NPROJ);
    // 3. FIR + split + IIR -> y, new_fir, new_iir (also zeroes g_ssq)
    fir_iir_kernel<<<256, 384>>>(pA, fir_state, sfw, sfb, iir_state, lp, resid, Dres, y, out);
    // 4. y @ out_w (4096x4096): 4 col x 64 chunks = 256 blocks
    gemv_partial<64><<<dim3(4,64), 256, smem64>>>(out_w, y, pA, DD, DD);
    // 5. xnew = reduce64 + out_b + x; accumulate sum of squares
    reduce_res_kernel<<<256, 256>>>((const float4*)pA, (const float4*)x,
                                    (const float4*)out_b, (float4*)xnew);
    // 6. xn2 = rmsnorm(xnew) * post_w
    scale_kernel<<<128, 256>>>(xnew, post_w, xn2);
    // 7. fused MLP up (4096x16384): 16 col x 16 chunks x 2 = 512 blocks
    gemv_dual<256><<<dim3(16,16,2), 256, smem256>>>(w1, w3, xn2, pA, pB, DD, FFD);
    // 8. SwiGLU gate
    glu_kernel<<<512, 256>>>((const float4*)pA, (const float4*)pB, (float4*)g);
    // 9. g @ mlp_w2 (16384x4096): 4 col x 64 chunks = 256 blocks
    gemv_partial<256><<<dim3(4,64), 256, smem256>>>(w2, g, pA, FFD, DD);
    // 10. x_out = xnew + reduce64
    final_kernel<<<256, 256>>>((const float4*)pA, (const float4*)xnew, (float4*)out);
}

// round 7
// speedup vs baseline: 1.2651x; 1.0345x over previous
#include <cuda_runtime.h>
#include <math.h>

// Problem constants
#define BB 8
#define DD 4096
#define NPROJ 12288      // 3*D
#define SS 16
#define FFD 16384
#define FIR_OFF 32768            // d_out offset of new_fir  (B*D elems of x first)
#define IIR_OFF 229376           // 32768 + 196608

typedef unsigned long long ull;

// ---------------- scratch (__device__ globals; no allocation allowed) -------
__device__ float g_xn1 [BB*DD];
__device__ float g_y   [BB*DD];
__device__ float g_xnew[BB*DD];
__device__ float g_g   [BB*FFD];
__device__ float g_ssq [BB];
__device__ float g_pA  [4194304];   // split-K partials
__device__ float g_pB  [4194304];

__device__ __forceinline__ void fma2(ull& a, ull w, ull x) {
    asm("fma.rn.f32x2 %0, %1, %2, %0;" : "+l"(a) : "l"(w), "l"(x));
}
__device__ __forceinline__ void cp_async16(void* sdst, const void* gsrc) {
    unsigned s = (unsigned)__cvta_generic_to_shared(sdst);
    asm volatile("cp.async.cg.shared.global [%0], [%1], 16;" :: "r"(s), "l"(gsrc));
}
__device__ __forceinline__ void cp_commit() {
    asm volatile("cp.async.commit_group;");
}
template<int N> __device__ __forceinline__ void cp_wait() {
    asm volatile("cp.async.wait_group %0;" :: "n"(N));
}

// ---------------- rmsnorm of input x ----------------------------------------
__global__ void rmsnorm1_kernel(const float* __restrict__ x,
                                const float* __restrict__ w,
                                float* __restrict__ out) {
    int b = blockIdx.x;          // 8 blocks
    int tid = threadIdx.x;       // 512 threads
    float v[8];
    float ss = 0.f;
#pragma unroll
    for (int e = 0; e < 8; e++) {
        float t = x[b*DD + e*512 + tid];
        v[e] = t; ss += t*t;
    }
    __shared__ float red[16];
    int lane = tid & 31, wid = tid >> 5;
#pragma unroll
    for (int o = 16; o; o >>= 1) ss += __shfl_xor_sync(0xffffffffu, ss, o);
    if (lane == 0) red[wid] = ss;
    __syncthreads();
    if (tid == 0) { float t = 0.f; for (int i = 0; i < 16; i++) t += red[i]; red[0] = t; }
    __syncthreads();
    float scale = rsqrtf(red[0] * (1.f/DD) + 1e-6f);
#pragma unroll
    for (int e = 0; e < 8; e++)
        out[b*DD + e*512 + tid] = v[e] * scale * w[e*512 + tid];
}

// ---------------- split-K GEMV: cp.async double-buffered smem staging -------
template<int KCH>
__global__ __launch_bounds__(256, 2)
void gemv_partial(const float* __restrict__ W,
                  const float* __restrict__ X,
                  float* __restrict__ P, int K, int N) {
    extern __shared__ char smem[];
    float2*     xs2  = reinterpret_cast<float2*>(smem);                 // 8*KCH
    ulonglong2* wbuf = reinterpret_cast<ulonglong2*>(smem + 8*KCH*8);   // 2*8*256

    int tid = threadIdx.x;               // 256 threads
    int k0  = blockIdx.y * KCH;
#pragma unroll
    for (int i = tid; i < 8*KCH; i += 256) {
        int b = i / KCH, k = i % KCH;
        float v = X[b*K + k0 + k];
        xs2[i] = make_float2(v, v);
    }
    __syncthreads();

    int Nv = N >> 2;                     // float4 columns
    int col4 = blockIdx.x*256 + tid;
    const float4* Wv = reinterpret_cast<const float4*>(W) + (size_t)k0*Nv + col4;

#pragma unroll
    for (int i = 0; i < 8; i++)
        cp_async16(&wbuf[(0*8 + i)*256 + tid], Wv + (size_t)i*Nv);
    cp_commit();
#pragma unroll
    for (int i = 0; i < 8; i++)
        cp_async16(&wbuf[(1*8 + i)*256 + tid], Wv + (size_t)(8+i)*Nv);
    cp_commit();

    ull acc[8][2];
#pragma unroll
    for (int b = 0; b < 8; b++) { acc[b][0] = 0ull; acc[b][1] = 0ull; }

    const int nstages = KCH / 8;
#pragma unroll 1
    for (int s = 0; s < nstages; s++) {
        if (s + 1 < nstages) cp_wait<1>(); else cp_wait<0>();
        int sb = s & 1;
        const ulonglong2* ws = wbuf + sb*2048 + tid;
        int kb = s*8;
#pragma unroll
        for (int i = 0; i < 8; i++) {
            ulonglong2 wv = ws[i*256];
#pragma unroll
            for (int b = 0; b < 8; b++) {
                ull xx = *reinterpret_cast<const ull*>(&xs2[b*KCH + kb + i]);
                fma2(acc[b][0], wv.x, xx);
                fma2(acc[b][1], wv.y, xx);
            }
        }
        if (s + 2 < nstages) {
            const float4* src = Wv + (size_t)(s+2)*8*Nv;
#pragma unroll
            for (int i = 0; i < 8; i++)
                cp_async16(&wbuf[(sb*8 + i)*256 + tid], src + (size_t)i*Nv);
            cp_commit();
        }
    }

    ulonglong2* Pv = reinterpret_cast<ulonglong2*>(P)
                   + (size_t)blockIdx.y*(N<<1) + col4;
#pragma unroll
    for (int b = 0; b < 8; b++)
        Pv[(size_t)b*Nv] = make_ulonglong2(acc[b][0], acc[b][1]);
}

// ---------------- dual GEMV for w1/w3 with fused post-norm scaling ----------
// activation = xnew[b][k] * rsqrt(ssq[b]/D + eps) * post_w[k]
template<int KCH>
__global__ __launch_bounds__(256, 2)
void gemv_dual(const float* __restrict__ W1,
               const float* __restrict__ W3,
               const float* __restrict__ Xnew,
               const float* __restrict__ PostW,
               float* __restrict__ P1,
               float* __restrict__ P3, int K, int N) {
    extern __shared__ char smem[];
    float2*     xs2  = reinterpret_cast<float2*>(smem);
    ulonglong2* wbuf = reinterpret_cast<ulonglong2*>(smem + 8*KCH*8);

    const float* W = blockIdx.z ? W3 : W1;
    float*       P = blockIdx.z ? P3 : P1;

    int tid = threadIdx.x;
    int k0  = blockIdx.y * KCH;
    float rs[BB];
#pragma unroll
    for (int b = 0; b < BB; b++)
        rs[b] = rsqrtf(g_ssq[b] * (1.f/DD) + 1e-6f);
#pragma unroll
    for (int i = tid; i < 8*KCH; i += 256) {
        int b = i / KCH, k = i % KCH;
        float v = Xnew[b*K + k0 + k] * rs[b] * PostW[k0 + k];
        xs2[i] = make_float2(v, v);
    }
    __syncthreads();

    int Nv = N >> 2;
    int col4 = blockIdx.x*256 + tid;
    const float4* Wv = reinterpret_cast<const float4*>(W) + (size_t)k0*Nv + col4;

#pragma unroll
    for (int i = 0; i < 8; i++)
        cp_async16(&wbuf[(0*8 + i)*256 + tid], Wv + (size_t)i*Nv);
    cp_commit();
#pragma unroll
    for (int i = 0; i < 8; i++)
        cp_async16(&wbuf[(1*8 + i)*256 + tid], Wv + (size_t)(8+i)*Nv);
    cp_commit();

    ull acc[8][2];
#pragma unroll
    for (int b = 0; b < 8; b++) { acc[b][0] = 0ull; acc[b][1] = 0ull; }

    const int nstages = KCH / 8;
#pragma unroll 1
    for (int s = 0; s < nstages; s++) {
        if (s + 1 < nstages) cp_wait<1>(); else cp_wait<0>();
        int sb = s & 1;
        const ulonglong2* ws = wbuf + sb*2048 + tid;
        int kb = s*8;
#pragma unroll
        for (int i = 0; i < 8; i++) {
            ulonglong2 wv = ws[i*256];
#pragma unroll
            for (int b = 0; b < 8; b++) {
                ull xx = *reinterpret_cast<const ull*>(&xs2[b*KCH + kb + i]);
                fma2(acc[b][0], wv.x, xx);
                fma2(acc[b][1], wv.y, xx);
            }
        }
        if (s + 2 < nstages) {
            const float4* src = Wv + (size_t)(s+2)*8*Nv;
#pragma unroll
            for (int i = 0; i < 8; i++)
                cp_async16(&wbuf[(sb*8 + i)*256 + tid], src + (size_t)i*Nv);
            cp_commit();
        }
    }

    ulonglong2* Pv = reinterpret_cast<ulonglong2*>(P)
                   + (size_t)blockIdx.y*(N<<1) + col4;
#pragma unroll
    for (int b = 0; b < 8; b++)
        Pv[(size_t)b*Nv] = make_ulonglong2(acc[b][0], acc[b][1]);
}

// ---------------- FIR + gating split + IIR (384 threads: 3 parallel gates) --
__global__ void fir_iir_kernel(const float* __restrict__ P,
                               const float* __restrict__ fir_state,
                               const float* __restrict__ sfw,
                               const float* __restrict__ sfb,
                               const float* __restrict__ iir,
                               const float* __restrict__ lp,
                               const float* __restrict__ resid,
                               const float* __restrict__ Dres,
                               float* __restrict__ y,
                               float* __restrict__ dout) {
    __shared__ float zps[384];
    int blk = blockIdx.x;                // 256 blocks = 8 batch * 32 heads
    int b = blk >> 5, h = blk & 31;
    int tid = threadIdx.x;               // 384 threads
    int e = tid >> 7, j = tid & 127;
    if (blk == 0 && tid < BB) g_ssq[tid] = 0.f;   // pre-zero for reduce_res

    {
        int i  = h*384 + e*128 + j;
        int gi = b*NPROJ + i;
        float u = 0.f;
#pragma unroll
        for (int c = 0; c < 16; c++) u += P[c*(8*NPROJ) + gi];
        float f0 = fir_state[gi*2 + 0];
        float f1 = fir_state[gi*2 + 1];
        float w0 = sfw[i*3 + 0], w1 = sfw[i*3 + 1], w2 = sfw[i*3 + 2];
        zps[tid] = w2*u + f0*w0 + f1*w1 + sfb[i];
        dout[FIR_OFF + gi*2 + 0] = f1;   // new_fir = [f1, u]
        dout[FIR_OFF + gi*2 + 1] = u;
    }
    __syncthreads();
    if (tid < 128) {
        int d = h*128 + tid;
        float x2 = zps[tid], x1 = zps[128+tid], v = zps[256+tid];
        float x1v = x1 * v;
        float res = 0.f;
        int base = (b*DD + d)*SS;
#pragma unroll
        for (int s = 0; s < SS; s++) {
            float pole = __expf(lp[d*SS + s]);
            float ni = fmaf(pole, iir[base + s], x1v);
            dout[IIR_OFF + base + s] = ni;
            res = fmaf(resid[d*SS + s], ni, res);
        }
        y[b*DD + d] = x2 * (res + Dres[d]*x1v);
    }
}

// ---------------- reduce out_w (64 chunks, 8-way split) + bias + res + ssq --
__global__ void reduce_res_kernel(const float4* __restrict__ P4,
                                  const float4* __restrict__ x4,
                                  const float4* __restrict__ ob4,
                                  float4* __restrict__ xnew4) {
    __shared__ float4 sp[8][32];
    int tid = threadIdx.x;               // 256: j = tid&31 element, sub = tid>>5
    int j = tid & 31, sub = tid >> 5;
    int e = blockIdx.x*32 + j;           // 256 blocks -> 8192 float4
    float4 v = make_float4(0,0,0,0);
#pragma unroll
    for (int i = 0; i < 8; i++) {
        float4 t = P4[(size_t)(sub*8 + i)*8192 + e];
        v.x += t.x; v.y += t.y; v.z += t.z; v.w += t.w;
    }
    sp[sub][j] = v;
    __syncthreads();
    if (sub == 0) {
        int b = e >> 10;
        float4 o = ob4[e & 1023];
        float4 r = x4[e];
        r.x += o.x; r.y += o.y; r.z += o.z; r.w += o.w;
#pragma unroll
        for (int s = 0; s < 8; s++) {
            float4 t = sp[s][j];
            r.x += t.x; r.y += t.y; r.z += t.z; r.w += t.w;
        }
        xnew4[e] = r;
        float ss = r.x*r.x + r.y*r.y + r.z*r.z + r.w*r.w;
#pragma unroll
        for (int o2 = 16; o2; o2 >>= 1) ss += __shfl_xor_sync(0xffffffffu, ss, o2);
        if (j == 0) atomicAdd(&g_ssq[b], ss);
    }
}

// ---------------- SwiGLU (8 chunks each, 4-way split x 2) --------------------
__global__ void glu_kernel(const float4* __restrict__ PA4,
                           const float4* __restrict__ PB4,
                           float4* __restrict__ g4out) {
    __shared__ float4 sa[4][64], sb[4][64];
    int tid = threadIdx.x;               // 256: j = tid&63, sub = tid>>6
    int j = tid & 63, sub = tid >> 6;
    int e = blockIdx.x*64 + j;           // 512 blocks -> 32768 float4
    float4 a = make_float4(0,0,0,0), c3 = make_float4(0,0,0,0);
#pragma unroll
    for (int i = 0; i < 2; i++) {
        float4 pa = PA4[(size_t)(sub*2 + i)*32768 + e];
        float4 pb = PB4[(size_t)(sub*2 + i)*32768 + e];
        a.x += pa.x; a.y += pa.y; a.z += pa.z; a.w += pa.w;
        c3.x += pb.x; c3.y += pb.y; c3.z += pb.z; c3.w += pb.w;
    }
    sa[sub][j] = a; sb[sub][j] = c3;
    __syncthreads();
    if (sub == 0) {
        float4 ra = make_float4(0,0,0,0), rb = make_float4(0,0,0,0);
#pragma unroll
        for (int s = 0; s < 4; s++) {
            float4 ta = sa[s][j], tb = sb[s][j];
            ra.x += ta.x; ra.y += ta.y; ra.z += ta.z; ra.w += ta.w;
            rb.x += tb.x; rb.y += tb.y; rb.z += tb.z; rb.w += tb.w;
        }
        float4 r;
        r.x = (ra.x / (1.f + __expf(-ra.x))) * rb.x;
        r.y = (ra.y / (1.f + __expf(-ra.y))) * rb.y;
        r.z = (ra.z / (1.f + __expf(-ra.z))) * rb.z;
        r.w = (ra.w / (1.f + __expf(-ra.w))) * rb.w;
        g4out[e] = r;
    }
}

// ---------------- final: x_out = xnew + reduce64 (8-way split) ---------------
__global__ void final_kernel(const float4* __restrict__ P4,
                             const float4* __restrict__ xnew4,
                             float4* __restrict__ dout4) {
    __shared__ float4 sp[8][32];
    int tid = threadIdx.x;
    int j = tid & 31, sub = tid >> 5;
    int e = blockIdx.x*32 + j;           // 256 blocks -> 8192 float4
    float4 v = make_float4(0,0,0,0);
#pragma unroll
    for (int i = 0; i < 8; i++) {
        float4 t = P4[(size_t)(sub*8 + i)*8192 + e];
        v.x += t.x; v.y += t.y; v.z += t.z; v.w += t.w;
    }
    sp[sub][j] = v;
    __syncthreads();
    if (sub == 0) {
        float4 r = xnew4[e];
#pragma unroll
        for (int s = 0; s < 8; s++) {
            float4 t = sp[s][j];
            r.x += t.x; r.y += t.y; r.z += t.z; r.w += t.w;
        }
        dout4[e] = r;
    }
}

// ---------------- host launcher ----------------------------------------------
extern "C" void kernel_launch(void* const* d_in, const int* in_sizes, int n_in,
                              void* d_out, int out_size) {
    (void)in_sizes; (void)n_in; (void)out_size;
    const float* x          = (const float*)d_in[0];
    const float* fir_state  = (const float*)d_in[1];
    const float* iir_state  = (const float*)d_in[2];
    const float* pre_w      = (const float*)d_in[3];
    const float* proj_w     = (const float*)d_in[4];
    const float* sfw        = (const float*)d_in[5];
    const float* sfb        = (const float*)d_in[6];
    const float* Dres       = (const float*)d_in[7];
    const float* resid      = (const float*)d_in[8];
    const float* lp         = (const float*)d_in[9];
    const float* out_w      = (const float*)d_in[10];
    const float* out_b      = (const float*)d_in[11];
    const float* post_w     = (const float*)d_in[12];
    const float* w1         = (const float*)d_in[13];
    const float* w3         = (const float*)d_in[14];
    const float* w2         = (const float*)d_in[15];
    float* out = (float*)d_out;

    float *xn1, *y, *xnew, *g, *pA, *pB;
    cudaGetSymbolAddress((void**)&xn1,  g_xn1);
    cudaGetSymbolAddress((void**)&y,    g_y);
    cudaGetSymbolAddress((void**)&xnew, g_xnew);
    cudaGetSymbolAddress((void**)&g,    g_g);
    cudaGetSymbolAddress((void**)&pA,   g_pA);
    cudaGetSymbolAddress((void**)&pB,   g_pB);

    // dynamic smem: xs2 (8*KCH*8 B) + weight stages (65536 B)
    const int smem256 = 8*256*8 + 65536;   // 81920
    const int smem64  = 8*64*8  + 65536;   // 69632
    const int smem512 = 8*512*8 + 65536;   // 98304
    cudaFuncSetAttribute(gemv_partial<256>,
                         cudaFuncAttributeMaxDynamicSharedMemorySize, smem256);
    cudaFuncSetAttribute(gemv_partial<64>,
                         cudaFuncAttributeMaxDynamicSharedMemorySize, smem64);
    cudaFuncSetAttribute(gemv_dual<512>,
                         cudaFuncAttributeMaxDynamicSharedMemorySize, smem512);

    // 1. pre-norm
    rmsnorm1_kernel<<<BB, 512>>>(x, pre_w, xn1);
    // 2. z = xn1 @ proj_w (4096x12288): 12 col x 16 chunks = 192 blocks
    gemv_partial<256><<<dim3(12,16), 256, smem256>>>(proj_w, xn1, pA, DD, NPROJ);
    // 3. FIR + split + IIR -> y, new_fir, new_iir (also zeroes g_ssq)
    fir_iir_kernel<<<256, 384>>>(pA, fir_state, sfw, sfb, iir_state, lp, resid, Dres, y, out);
    // 4. y @ out_w (4096x4096): 4 col x 64 chunks = 256 blocks
    gemv_partial<64><<<dim3(4,64), 256, smem64>>>(out_w, y, pA, DD, DD);
    // 5. xnew = reduce64 + out_b + x; accumulate sum of squares
    reduce_res_kernel<<<256, 256>>>((const float4*)pA, (const float4*)x,
                                    (const float4*)out_b, (float4*)xnew);
    // 6. fused MLP up with post-norm (4096x16384): 16 col x 8 chunks x 2 = 256 blocks
    gemv_dual<512><<<dim3(16,8,2), 256, smem512>>>(w1, w3, xnew, post_w, pA, pB, DD, FFD);
    // 7. SwiGLU gate (8 chunks)
    glu_kernel<<<512, 256>>>((const float4*)pA, (const float4*)pB, (float4*)g);
    // 8. g @ mlp_w2 (16384x4096): 4 col x 64 chunks = 256 blocks
    gemv_partial<256><<<dim3(4,64), 256, smem256>>>(w2, g, pA, FFD, DD);
    // 9. x_out = xnew + reduce64
    final_kernel<<<256, 256>>>((const float4*)pA, (const float4*)xnew, (float4*)out);
}

// round 8
// speedup vs baseline: 1.2702x; 1.0040x over previous
#include <cuda_runtime.h>
#include <math.h>

// Problem constants
#define BB 8
#define DD 4096
#define NPROJ 12288      // 3*D
#define SS 16
#define FFD 16384
#define FIR_OFF 32768            // d_out offset of new_fir  (B*D elems of x first)
#define IIR_OFF 229376           // 32768 + 196608

typedef unsigned long long ull;

// ---------------- scratch (__device__ globals; no allocation allowed) -------
__device__ float g_xn1 [BB*DD];
__device__ float g_y   [BB*DD];
__device__ float g_xnew[BB*DD];
__device__ float g_g   [BB*FFD];
__device__ float g_ssq [BB];
__device__ float g_pA  [4194304];   // split-K partials
__device__ float g_pB  [4194304];

__device__ __forceinline__ void fma2(ull& a, ull w, ull x) {
    asm("fma.rn.f32x2 %0, %1, %2, %0;" : "+l"(a) : "l"(w), "l"(x));
}
__device__ __forceinline__ void cp_async16(void* sdst, const void* gsrc) {
    unsigned s = (unsigned)__cvta_generic_to_shared(sdst);
    asm volatile("cp.async.cg.shared.global [%0], [%1], 16;" :: "r"(s), "l"(gsrc));
}
__device__ __forceinline__ void cp_commit() {
    asm volatile("cp.async.commit_group;");
}
template<int N> __device__ __forceinline__ void cp_wait() {
    asm volatile("cp.async.wait_group %0;" :: "n"(N));
}
// PDL controls
__device__ __forceinline__ void pdl_wait() {
    asm volatile("griddepcontrol.wait;" ::: "memory");
}
__device__ __forceinline__ void pdl_trigger() {
    asm volatile("griddepcontrol.launch_dependents;");
}

// ---------------- rmsnorm of input x ----------------------------------------
__global__ void rmsnorm1_kernel(const float* __restrict__ x,
                                const float* __restrict__ w,
                                float* __restrict__ out) {
    pdl_trigger();               // let proj_w GEMV start prefetching weights
    int b = blockIdx.x;          // 8 blocks
    int tid = threadIdx.x;       // 512 threads
    float v[8];
    float ss = 0.f;
#pragma unroll
    for (int e = 0; e < 8; e++) {
        float t = x[b*DD + e*512 + tid];
        v[e] = t; ss += t*t;
    }
    __shared__ float red[16];
    int lane = tid & 31, wid = tid >> 5;
#pragma unroll
    for (int o = 16; o; o >>= 1) ss += __shfl_xor_sync(0xffffffffu, ss, o);
    if (lane == 0) red[wid] = ss;
    __syncthreads();
    if (tid == 0) { float t = 0.f; for (int i = 0; i < 16; i++) t += red[i]; red[0] = t; }
    __syncthreads();
    float scale = rsqrtf(red[0] * (1.f/DD) + 1e-6f);
#pragma unroll
    for (int e = 0; e < 8; e++)
        out[b*DD + e*512 + tid] = v[e] * scale * w[e*512 + tid];
}

// ---------------- split-K GEMV: cp.async double-buffered smem staging -------
// weight prefetch issued BEFORE pdl_wait so it overlaps the predecessor kernel
template<int KCH>
__global__ __launch_bounds__(256, 2)
void gemv_partial(const float* __restrict__ W,
                  const float* __restrict__ X,
                  float* __restrict__ P, int K, int N) {
    extern __shared__ char smem[];
    float2*     xs2  = reinterpret_cast<float2*>(smem);                 // 8*KCH
    ulonglong2* wbuf = reinterpret_cast<ulonglong2*>(smem + 8*KCH*8);   // 2*8*256

    int tid = threadIdx.x;               // 256 threads
    int k0  = blockIdx.y * KCH;
    int Nv = N >> 2;                     // float4 columns
    int col4 = blockIdx.x*256 + tid;
    const float4* Wv = reinterpret_cast<const float4*>(W) + (size_t)k0*Nv + col4;

    // weight prefetch (independent of predecessor output)
#pragma unroll
    for (int i = 0; i < 8; i++)
        cp_async16(&wbuf[(0*8 + i)*256 + tid], Wv + (size_t)i*Nv);
    cp_commit();
#pragma unroll
    for (int i = 0; i < 8; i++)
        cp_async16(&wbuf[(1*8 + i)*256 + tid], Wv + (size_t)(8+i)*Nv);
    cp_commit();

    pdl_trigger();
    pdl_wait();                          // predecessor output (X) now visible

#pragma unroll
    for (int i = tid; i < 8*KCH; i += 256) {
        int b = i / KCH, k = i % KCH;
        float v = X[b*K + k0 + k];
        xs2[i] = make_float2(v, v);
    }
    __syncthreads();

    ull acc[8][2];
#pragma unroll
    for (int b = 0; b < 8; b++) { acc[b][0] = 0ull; acc[b][1] = 0ull; }

    const int nstages = KCH / 8;
#pragma unroll 1
    for (int s = 0; s < nstages; s++) {
        if (s + 1 < nstages) cp_wait<1>(); else cp_wait<0>();
        int sb = s & 1;
        const ulonglong2* ws = wbuf + sb*2048 + tid;
        int kb = s*8;
#pragma unroll
        for (int i = 0; i < 8; i++) {
            ulonglong2 wv = ws[i*256];
#pragma unroll
            for (int b = 0; b < 8; b++) {
                ull xx = *reinterpret_cast<const ull*>(&xs2[b*KCH + kb + i]);
                fma2(acc[b][0], wv.x, xx);
                fma2(acc[b][1], wv.y, xx);
            }
        }
        if (s + 2 < nstages) {
            const float4* src = Wv + (size_t)(s+2)*8*Nv;
#pragma unroll
            for (int i = 0; i < 8; i++)
                cp_async16(&wbuf[(sb*8 + i)*256 + tid], src + (size_t)i*Nv);
            cp_commit();
        }
    }

    ulonglong2* Pv = reinterpret_cast<ulonglong2*>(P)
                   + (size_t)blockIdx.y*(N<<1) + col4;
#pragma unroll
    for (int b = 0; b < 8; b++)
        Pv[(size_t)b*Nv] = make_ulonglong2(acc[b][0], acc[b][1]);
}

// ---------------- dual GEMV for w1/w3 with fused post-norm scaling ----------
template<int KCH>
__global__ __launch_bounds__(256, 2)
void gemv_dual(const float* __restrict__ W1,
               const float* __restrict__ W3,
               const float* __restrict__ Xnew,
               const float* __restrict__ PostW,
               float* __restrict__ P1,
               float* __restrict__ P3, int K, int N) {
    extern __shared__ char smem[];
    float2*     xs2  = reinterpret_cast<float2*>(smem);
    ulonglong2* wbuf = reinterpret_cast<ulonglong2*>(smem + 8*KCH*8);

    const float* W = blockIdx.z ? W3 : W1;
    float*       P = blockIdx.z ? P3 : P1;

    int tid = threadIdx.x;
    int k0  = blockIdx.y * KCH;
    int Nv = N >> 2;
    int col4 = blockIdx.x*256 + tid;
    const float4* Wv = reinterpret_cast<const float4*>(W) + (size_t)k0*Nv + col4;

    // weight prefetch before dependency wait
#pragma unroll
    for (int i = 0; i < 8; i++)
        cp_async16(&wbuf[(0*8 + i)*256 + tid], Wv + (size_t)i*Nv);
    cp_commit();
#pragma unroll
    for (int i = 0; i < 8; i++)
        cp_async16(&wbuf[(1*8 + i)*256 + tid], Wv + (size_t)(8+i)*Nv);
    cp_commit();

    pdl_trigger();
    pdl_wait();                          // xnew + g_ssq now valid

    float rs[BB];
#pragma unroll
    for (int b = 0; b < BB; b++)
        rs[b] = rsqrtf(g_ssq[b] * (1.f/DD) + 1e-6f);
#pragma unroll
    for (int i = tid; i < 8*KCH; i += 256) {
        int b = i / KCH, k = i % KCH;
        float v = Xnew[b*K + k0 + k] * rs[b] * PostW[k0 + k];
        xs2[i] = make_float2(v, v);
    }
    __syncthreads();

    ull acc[8][2];
#pragma unroll
    for (int b = 0; b < 8; b++) { acc[b][0] = 0ull; acc[b][1] = 0ull; }

    const int nstages = KCH / 8;
#pragma unroll 1
    for (int s = 0; s < nstages; s++) {
        if (s + 1 < nstages) cp_wait<1>(); else cp_wait<0>();
        int sb = s & 1;
        const ulonglong2* ws = wbuf + sb*2048 + tid;
        int kb = s*8;
#pragma unroll
        for (int i = 0; i < 8; i++) {
            ulonglong2 wv = ws[i*256];
#pragma unroll
            for (int b = 0; b < 8; b++) {
                ull xx = *reinterpret_cast<const ull*>(&xs2[b*KCH + kb + i]);
                fma2(acc[b][0], wv.x, xx);
                fma2(acc[b][1], wv.y, xx);
            }
        }
        if (s + 2 < nstages) {
            const float4* src = Wv + (size_t)(s+2)*8*Nv;
#pragma unroll
            for (int i = 0; i < 8; i++)
                cp_async16(&wbuf[(sb*8 + i)*256 + tid], src + (size_t)i*Nv);
            cp_commit();
        }
    }

    ulonglong2* Pv = reinterpret_cast<ulonglong2*>(P)
                   + (size_t)blockIdx.y*(N<<1) + col4;
#pragma unroll
    for (int b = 0; b < 8; b++)
        Pv[(size_t)b*Nv] = make_ulonglong2(acc[b][0], acc[b][1]);
}

// ---------------- FIR + gating split + IIR (384 threads: 3 parallel gates) --
__global__ void fir_iir_kernel(const float* __restrict__ P,
                               const float* __restrict__ fir_state,
                               const float* __restrict__ sfw,
                               const float* __restrict__ sfb,
                               const float* __restrict__ iir,
                               const float* __restrict__ lp,
                               const float* __restrict__ resid,
                               const float* __restrict__ Dres,
                               float* __restrict__ y,
                               float* __restrict__ dout) {
    __shared__ float zps[384];
    pdl_trigger();                       // let out_w GEMV prefetch weights now
    pdl_wait();                          // proj partials ready
    int blk = blockIdx.x;                // 256 blocks = 8 batch * 32 heads
    int b = blk >> 5, h = blk & 31;
    int tid = threadIdx.x;               // 384 threads
    int e = tid >> 7, j = tid & 127;
    if (blk == 0 && tid < BB) g_ssq[tid] = 0.f;   // pre-zero for reduce_res

    {
        int i  = h*384 + e*128 + j;
        int gi = b*NPROJ + i;
        float u = 0.f;
#pragma unroll
        for (int c = 0; c < 16; c++) u += P[c*(8*NPROJ) + gi];
        float f0 = fir_state[gi*2 + 0];
        float f1 = fir_state[gi*2 + 1];
        float w0 = sfw[i*3 + 0], w1 = sfw[i*3 + 1], w2 = sfw[i*3 + 2];
        zps[tid] = w2*u + f0*w0 + f1*w1 + sfb[i];
        dout[FIR_OFF + gi*2 + 0] = f1;   // new_fir = [f1, u]
        dout[FIR_OFF + gi*2 + 1] = u;
    }
    __syncthreads();
    if (tid < 128) {
        int d = h*128 + tid;
        float x2 = zps[tid], x1 = zps[128+tid], v = zps[256+tid];
        float x1v = x1 * v;
        float res = 0.f;
        int base = (b*DD + d)*SS;
#pragma unroll
        for (int s = 0; s < SS; s++) {
            float pole = __expf(lp[d*SS + s]);
            float ni = fmaf(pole, iir[base + s], x1v);
            dout[IIR_OFF + base + s] = ni;
            res = fmaf(resid[d*SS + s], ni, res);
        }
        y[b*DD + d] = x2 * (res + Dres[d]*x1v);
    }
}

// ---------------- reduce out_w (64 chunks, 8-way split) + bias + res + ssq --
__global__ void reduce_res_kernel(const float4* __restrict__ P4,
                                  const float4* __restrict__ x4,
                                  const float4* __restrict__ ob4,
                                  float4* __restrict__ xnew4) {
    __shared__ float4 sp[8][32];
    pdl_trigger();                       // let dual GEMV prefetch w1/w3 now
    pdl_wait();
    int tid = threadIdx.x;               // 256: j = tid&31 element, sub = tid>>5
    int j = tid & 31, sub = tid >> 5;
    int e = blockIdx.x*32 + j;           // 256 blocks -> 8192 float4
    float4 v = make_float4(0,0,0,0);
#pragma unroll
    for (int i = 0; i < 8; i++) {
        float4 t = P4[(size_t)(sub*8 + i)*8192 + e];
        v.x += t.x; v.y += t.y; v.z += t.z; v.w += t.w;
    }
    sp[sub][j] = v;
    __syncthreads();
    if (sub == 0) {
        int b = e >> 10;
        float4 o = ob4[e & 1023];
        float4 r = x4[e];
        r.x += o.x; r.y += o.y; r.z += o.z; r.w += o.w;
#pragma unroll
        for (int s = 0; s < 8; s++) {
            float4 t = sp[s][j];
            r.x += t.x; r.y += t.y; r.z += t.z; r.w += t.w;
        }
        xnew4[e] = r;
        float ss = r.x*r.x + r.y*r.y + r.z*r.z + r.w*r.w;
#pragma unroll
        for (int o2 = 16; o2; o2 >>= 1) ss += __shfl_xor_sync(0xffffffffu, ss, o2);
        if (j == 0) atomicAdd(&g_ssq[b], ss);
    }
}

// ---------------- SwiGLU (8 chunks each, 4-way split x 2) --------------------
__global__ void glu_kernel(const float4* __restrict__ PA4,
                           const float4* __restrict__ PB4,
                           float4* __restrict__ g4out) {
    __shared__ float4 sa[4][64], sb[4][64];
    pdl_trigger();                       // let w2 GEMV prefetch weights now
    pdl_wait();
    int tid = threadIdx.x;               // 256: j = tid&63, sub = tid>>6
    int j = tid & 63, sub = tid >> 6;
    int e = blockIdx.x*64 + j;           // 512 blocks -> 32768 float4
    float4 a = make_float4(0,0,0,0), c3 = make_float4(0,0,0,0);
#pragma unroll
    for (int i = 0; i < 2; i++) {
        float4 pa = PA4[(size_t)(sub*2 + i)*32768 + e];
        float4 pb = PB4[(size_t)(sub*2 + i)*32768 + e];
        a.x += pa.x; a.y += pa.y; a.z += pa.z; a.w += pa.w;
        c3.x += pb.x; c3.y += pb.y; c3.z += pb.z; c3.w += pb.w;
    }
    sa[sub][j] = a; sb[sub][j] = c3;
    __syncthreads();
    if (sub == 0) {
        float4 ra = make_float4(0,0,0,0), rb = make_float4(0,0,0,0);
#pragma unroll
        for (int s = 0; s < 4; s++) {
            float4 ta = sa[s][j], tb = sb[s][j];
            ra.x += ta.x; ra.y += ta.y; ra.z += ta.z; ra.w += ta.w;
            rb.x += tb.x; rb.y += tb.y; rb.z += tb.z; rb.w += tb.w;
        }
        float4 r;
        r.x = (ra.x / (1.f + __expf(-ra.x))) * rb.x;
        r.y = (ra.y / (1.f + __expf(-ra.y))) * rb.y;
        r.z = (ra.z / (1.f + __expf(-ra.z))) * rb.z;
        r.w = (ra.w / (1.f + __expf(-ra.w))) * rb.w;
        g4out[e] = r;
    }
}

// ---------------- final: x_out = xnew + reduce64 (8-way split) ---------------
__global__ void final_kernel(const float4* __restrict__ P4,
                             const float4* __restrict__ xnew4,
                             float4* __restrict__ dout4) {
    __shared__ float4 sp[8][32];
    pdl_trigger();
    pdl_wait();
    int tid = threadIdx.x;
    int j = tid & 31, sub = tid >> 5;
    int e = blockIdx.x*32 + j;           // 256 blocks -> 8192 float4
    float4 v = make_float4(0,0,0,0);
#pragma unroll
    for (int i = 0; i < 8; i++) {
        float4 t = P4[(size_t)(sub*8 + i)*8192 + e];
        v.x += t.x; v.y += t.y; v.z += t.z; v.w += t.w;
    }
    sp[sub][j] = v;
    __syncthreads();
    if (sub == 0) {
        float4 r = xnew4[e];
#pragma unroll
        for (int s = 0; s < 8; s++) {
            float4 t = sp[s][j];
            r.x += t.x; r.y += t.y; r.z += t.z; r.w += t.w;
        }
        dout4[e] = r;
    }
}

// ---------------- host launcher ----------------------------------------------
static void launch_pdl(const void* func, dim3 grid, dim3 block, size_t smem,
                       void** args) {
    cudaLaunchConfig_t cfg = {};
    cfg.gridDim = grid;
    cfg.blockDim = block;
    cfg.dynamicSmemBytes = smem;
    cfg.stream = 0;
    cudaLaunchAttribute attr[1];
    attr[0].id = cudaLaunchAttributeProgrammaticStreamSerialization;
    attr[0].val.programmaticStreamSerializationAllowed = 1;
    cfg.attrs = attr;
    cfg.numAttrs = 1;
    cudaLaunchKernelExC(&cfg, func, args);
}

extern "C" void kernel_launch(void* const* d_in, const int* in_sizes, int n_in,
                              void* d_out, int out_size) {
    (void)in_sizes; (void)n_in; (void)out_size;
    const float* x          = (const float*)d_in[0];
    const float* fir_state  = (const float*)d_in[1];
    const float* iir_state  = (const float*)d_in[2];
    const float* pre_w      = (const float*)d_in[3];
    const float* proj_w     = (const float*)d_in[4];
    const float* sfw        = (const float*)d_in[5];
    const float* sfb        = (const float*)d_in[6];
    const float* Dres       = (const float*)d_in[7];
    const float* resid      = (const float*)d_in[8];
    const float* lp         = (const float*)d_in[9];
    const float* out_w      = (const float*)d_in[10];
    const float* out_b      = (const float*)d_in[11];
    const float* post_w     = (const float*)d_in[12];
    const float* w1         = (const float*)d_in[13];
    const float* w3         = (const float*)d_in[14];
    const float* w2         = (const float*)d_in[15];
    float* out = (float*)d_out;

    float *xn1, *y, *xnew, *g, *pA, *pB;
    cudaGetSymbolAddress((void**)&xn1,  g_xn1);
    cudaGetSymbolAddress((void**)&y,    g_y);
    cudaGetSymbolAddress((void**)&xnew, g_xnew);
    cudaGetSymbolAddress((void**)&g,    g_g);
    cudaGetSymbolAddress((void**)&pA,   g_pA);
    cudaGetSymbolAddress((void**)&pB,   g_pB);

    // dynamic smem: xs2 (8*KCH*8 B) + weight stages (65536 B)
    const int smem256 = 8*256*8 + 65536;   // 81920
    const int smem64  = 8*64*8  + 65536;   // 69632
    const int smem512 = 8*512*8 + 65536;   // 98304
    cudaFuncSetAttribute(gemv_partial<256>,
                         cudaFuncAttributeMaxDynamicSharedMemorySize, smem256);
    cudaFuncSetAttribute(gemv_partial<64>,
                         cudaFuncAttributeMaxDynamicSharedMemorySize, smem64);
    cudaFuncSetAttribute(gemv_dual<512>,
                         cudaFuncAttributeMaxDynamicSharedMemorySize, smem512);

    int K1 = DD, N1 = NPROJ, N2 = DD, N3 = FFD, K3 = FFD;

    // 1. pre-norm (normal launch: acts as the per-replay ordering barrier)
    rmsnorm1_kernel<<<BB, 512>>>(x, pre_w, xn1);

    // 2. z = xn1 @ proj_w: 12 col x 16 chunks = 192 blocks
    {
        void* a[] = {&proj_w, &xn1, &pA, &K1, &N1};
        launch_pdl((const void*)gemv_partial<256>, dim3(12,16), dim3(256), smem256, a);
    }
    // 3. FIR + split + IIR -> y, new_fir, new_iir (also zeroes g_ssq)
    {
        void* a[] = {&pA, &fir_state, &sfw, &sfb, &iir_state, &lp, &resid, &Dres, &y, &out};
        launch_pdl((const void*)fir_iir_kernel, dim3(256), dim3(384), 0, a);
    }
    // 4. y @ out_w: 4 col x 64 chunks = 256 blocks
    {
        void* a[] = {&out_w, &y, &pA, &K1, &N2};
        launch_pdl((const void*)gemv_partial<64>, dim3(4,64), dim3(256), smem64, a);
    }
    // 5. xnew = reduce64 + out_b + x; accumulate sum of squares
    {
        const float4 *p4 = (const float4*)pA, *x4 = (const float4*)x,
                     *o4 = (const float4*)out_b;
        float4* xn4 = (float4*)xnew;
        void* a[] = {&p4, &x4, &o4, &xn4};
        launch_pdl((const void*)reduce_res_kernel, dim3(256), dim3(256), 0, a);
    }
    // 6. fused MLP up with post-norm: 16 col x 8 chunks x 2 = 256 blocks
    {
        void* a[] = {&w1, &w3, &xnew, &post_w, &pA, &pB, &K1, &N3};
        launch_pdl((const void*)gemv_dual<512>, dim3(16,8,2), dim3(256), smem512, a);
    }
    // 7. SwiGLU gate
    {
        const float4 *pa4 = (const float4*)pA, *pb4 = (const float4*)pB;
        float4* g4 = (float4*)g;
        void* a[] = {&pa4, &pb4, &g4};
        launch_pdl((const void*)glu_kernel, dim3(512), dim3(256), 0, a);
    }
    // 8. g @ mlp_w2: 4 col x 64 chunks = 256 blocks
    {
        void* a[] = {&w2, &g, &pA, &K3, &N2};
        launch_pdl((const void*)gemv_partial<256>, dim3(4,64), dim3(256), smem256, a);
    }
    // 9. x_out = xnew + reduce64
    {
        const float4 *p4 = (const float4*)pA, *xn4c = (const float4*)xnew;
        float4* d4 = (float4*)out;
        void* a[] = {&p4, &xn4c, &d4};
        launch_pdl((const void*)final_kernel, dim3(256), dim3(256), 0, a);
    }
}

// round 9
// speedup vs baseline: 1.3210x; 1.0400x over previous
#include <cuda_runtime.h>
#include <math.h>

// Problem constants
#define BB 8
#define DD 4096
#define NPROJ 12288      // 3*D
#define SS 16
#define FFD 16384
#define FIR_OFF 32768            // d_out offset of new_fir  (B*D elems of x first)
#define IIR_OFF 229376           // 32768 + 196608

typedef unsigned long long ull;

// ---------------- scratch (__device__ globals; no allocation allowed) -------
__device__ float g_xn1 [BB*DD];
__device__ float g_y   [BB*DD];
__device__ float g_xnew[BB*DD];
__device__ float g_g   [BB*FFD];
__device__ float g_ssq [BB];
// accumulators (atomically reduced GEMV outputs) — all L2-resident sized
__device__ float g_accP [BB*NPROJ];   // proj   (0.39 MB)
__device__ float g_accO [BB*DD];      // out_w  (0.13 MB)
__device__ float g_accW1[BB*FFD];     // mlp_w1 (0.5 MB)
__device__ float g_accW3[BB*FFD];     // mlp_w3 (0.5 MB)
__device__ float g_accW2[BB*DD];      // mlp_w2 (0.13 MB)

__device__ __forceinline__ void fma2(ull& a, ull w, ull x) {
    asm("fma.rn.f32x2 %0, %1, %2, %0;" : "+l"(a) : "l"(w), "l"(x));
}
__device__ __forceinline__ void cp_async16(void* sdst, const void* gsrc) {
    unsigned s = (unsigned)__cvta_generic_to_shared(sdst);
    asm volatile("cp.async.cg.shared.global [%0], [%1], 16;" :: "r"(s), "l"(gsrc));
}
__device__ __forceinline__ void cp_commit() {
    asm volatile("cp.async.commit_group;");
}
template<int N> __device__ __forceinline__ void cp_wait() {
    asm volatile("cp.async.wait_group %0;" :: "n"(N));
}
// PDL controls
__device__ __forceinline__ void pdl_wait() {
    asm volatile("griddepcontrol.wait;" ::: "memory");
}
__device__ __forceinline__ void pdl_trigger() {
    asm volatile("griddepcontrol.launch_dependents;");
}

// ---------------- rmsnorm of input x  (+ zero proj accumulator) -------------
__global__ void rmsnorm1_kernel(const float* __restrict__ x,
                                const float* __restrict__ w,
                                float* __restrict__ out,
                                float4* __restrict__ accP4) {
    int b = blockIdx.x;          // 8 blocks
    int tid = threadIdx.x;       // 512 threads
    // zero proj accumulator: 24576 float4 over 4096 threads = 6 each
    int gt = b*512 + tid;
    float4 z4 = make_float4(0.f,0.f,0.f,0.f);
#pragma unroll
    for (int i = 0; i < 6; i++) accP4[gt + i*4096] = z4;
    pdl_trigger();
    float v[8];
    float ss = 0.f;
#pragma unroll
    for (int e = 0; e < 8; e++) {
        float t = x[b*DD + e*512 + tid];
        v[e] = t; ss += t*t;
    }
    __shared__ float red[16];
    int lane = tid & 31, wid = tid >> 5;
#pragma unroll
    for (int o = 16; o; o >>= 1) ss += __shfl_xor_sync(0xffffffffu, ss, o);
    if (lane == 0) red[wid] = ss;
    __syncthreads();
    if (tid == 0) { float t = 0.f; for (int i = 0; i < 16; i++) t += red[i]; red[0] = t; }
    __syncthreads();
    float scale = rsqrtf(red[0] * (1.f/DD) + 1e-6f);
#pragma unroll
    for (int e = 0; e < 8; e++)
        out[b*DD + e*512 + tid] = v[e] * scale * w[e*512 + tid];
}

// ---------------- split-K GEMV -> atomic float4 accumulation ----------------
template<int KCH>
__global__ __launch_bounds__(256, 2)
void gemv_partial(const float* __restrict__ W,
                  const float* __restrict__ X,
                  float* __restrict__ P, int K, int N) {
    extern __shared__ char smem[];
    float2*     xs2  = reinterpret_cast<float2*>(smem);                 // 8*KCH
    ulonglong2* wbuf = reinterpret_cast<ulonglong2*>(smem + 8*KCH*8);   // 2*8*256

    int tid = threadIdx.x;               // 256 threads
    int k0  = blockIdx.y * KCH;
    int Nv = N >> 2;                     // float4 columns
    int col4 = blockIdx.x*256 + tid;
    const float4* Wv = reinterpret_cast<const float4*>(W) + (size_t)k0*Nv + col4;

    // weight prefetch (independent of predecessor output)
#pragma unroll
    for (int i = 0; i < 8; i++)
        cp_async16(&wbuf[(0*8 + i)*256 + tid], Wv + (size_t)i*Nv);
    cp_commit();
#pragma unroll
    for (int i = 0; i < 8; i++)
        cp_async16(&wbuf[(1*8 + i)*256 + tid], Wv + (size_t)(8+i)*Nv);
    cp_commit();

    pdl_trigger();
    pdl_wait();                          // predecessor output (X, zeroed P) visible

#pragma unroll
    for (int i = tid; i < 8*KCH; i += 256) {
        int b = i / KCH, k = i % KCH;
        float v = X[b*K + k0 + k];
        xs2[i] = make_float2(v, v);
    }
    __syncthreads();

    ull acc[8][2];
#pragma unroll
    for (int b = 0; b < 8; b++) { acc[b][0] = 0ull; acc[b][1] = 0ull; }

    const int nstages = KCH / 8;
#pragma unroll 1
    for (int s = 0; s < nstages; s++) {
        if (s + 1 < nstages) cp_wait<1>(); else cp_wait<0>();
        int sb = s & 1;
        const ulonglong2* ws = wbuf + sb*2048 + tid;
        int kb = s*8;
#pragma unroll
        for (int i = 0; i < 8; i++) {
            ulonglong2 wv = ws[i*256];
#pragma unroll
            for (int b = 0; b < 8; b++) {
                ull xx = *reinterpret_cast<const ull*>(&xs2[b*KCH + kb + i]);
                fma2(acc[b][0], wv.x, xx);
                fma2(acc[b][1], wv.y, xx);
            }
        }
        if (s + 2 < nstages) {
            const float4* src = Wv + (size_t)(s+2)*8*Nv;
#pragma unroll
            for (int i = 0; i < 8; i++)
                cp_async16(&wbuf[(sb*8 + i)*256 + tid], src + (size_t)i*Nv);
            cp_commit();
        }
    }

    float4* Pv = reinterpret_cast<float4*>(P) + col4;
#pragma unroll
    for (int b = 0; b < 8; b++) {
        float4 v;
        *reinterpret_cast<ull*>(&v.x) = acc[b][0];
        *reinterpret_cast<ull*>(&v.z) = acc[b][1];
        atomicAdd(&Pv[(size_t)b*Nv], v);
    }
}

// ---------------- dual GEMV for w1/w3 with fused post-norm scaling ----------
template<int KCH>
__global__ __launch_bounds__(256, 2)
void gemv_dual(const float* __restrict__ W1,
               const float* __restrict__ W3,
               const float* __restrict__ Xnew,
               const float* __restrict__ PostW,
               float* __restrict__ P1,
               float* __restrict__ P3, int K, int N) {
    extern __shared__ char smem[];
    float2*     xs2  = reinterpret_cast<float2*>(smem);
    ulonglong2* wbuf = reinterpret_cast<ulonglong2*>(smem + 8*KCH*8);

    const float* W = blockIdx.z ? W3 : W1;
    float*       P = blockIdx.z ? P3 : P1;

    int tid = threadIdx.x;
    int k0  = blockIdx.y * KCH;
    int Nv = N >> 2;
    int col4 = blockIdx.x*256 + tid;
    const float4* Wv = reinterpret_cast<const float4*>(W) + (size_t)k0*Nv + col4;

#pragma unroll
    for (int i = 0; i < 8; i++)
        cp_async16(&wbuf[(0*8 + i)*256 + tid], Wv + (size_t)i*Nv);
    cp_commit();
#pragma unroll
    for (int i = 0; i < 8; i++)
        cp_async16(&wbuf[(1*8 + i)*256 + tid], Wv + (size_t)(8+i)*Nv);
    cp_commit();

    pdl_trigger();
    pdl_wait();                          // xnew + g_ssq + zeroed accums valid

    float rs[BB];
#pragma unroll
    for (int b = 0; b < BB; b++)
        rs[b] = rsqrtf(g_ssq[b] * (1.f/DD) + 1e-6f);
#pragma unroll
    for (int i = tid; i < 8*KCH; i += 256) {
        int b = i / KCH, k = i % KCH;
        float v = Xnew[b*K + k0 + k] * rs[b] * PostW[k0 + k];
        xs2[i] = make_float2(v, v);
    }
    __syncthreads();

    ull acc[8][2];
#pragma unroll
    for (int b = 0; b < 8; b++) { acc[b][0] = 0ull; acc[b][1] = 0ull; }

    const int nstages = KCH / 8;
#pragma unroll 1
    for (int s = 0; s < nstages; s++) {
        if (s + 1 < nstages) cp_wait<1>(); else cp_wait<0>();
        int sb = s & 1;
        const ulonglong2* ws = wbuf + sb*2048 + tid;
        int kb = s*8;
#pragma unroll
        for (int i = 0; i < 8; i++) {
            ulonglong2 wv = ws[i*256];
#pragma unroll
            for (int b = 0; b < 8; b++) {
                ull xx = *reinterpret_cast<const ull*>(&xs2[b*KCH + kb + i]);
                fma2(acc[b][0], wv.x, xx);
                fma2(acc[b][1], wv.y, xx);
            }
        }
        if (s + 2 < nstages) {
            const float4* src = Wv + (size_t)(s+2)*8*Nv;
#pragma unroll
            for (int i = 0; i < 8; i++)
                cp_async16(&wbuf[(sb*8 + i)*256 + tid], src + (size_t)i*Nv);
            cp_commit();
        }
    }

    float4* Pv = reinterpret_cast<float4*>(P) + col4;
#pragma unroll
    for (int b = 0; b < 8; b++) {
        float4 v;
        *reinterpret_cast<ull*>(&v.x) = acc[b][0];
        *reinterpret_cast<ull*>(&v.z) = acc[b][1];
        atomicAdd(&Pv[(size_t)b*Nv], v);
    }
}

// ---------------- FIR + gating split + IIR (single-read z, zero accO) -------
__global__ void fir_iir_kernel(const float* __restrict__ P,
                               const float* __restrict__ fir_state,
                               const float* __restrict__ sfw,
                               const float* __restrict__ sfb,
                               const float* __restrict__ iir,
                               const float* __restrict__ lp,
                               const float* __restrict__ resid,
                               const float* __restrict__ Dres,
                               float* __restrict__ y,
                               float* __restrict__ dout,
                               float4* __restrict__ accO4) {
    __shared__ float zps[384];
    pdl_trigger();
    pdl_wait();                          // proj accumulation complete
    int blk = blockIdx.x;                // 256 blocks = 8 batch * 32 heads
    int b = blk >> 5, h = blk & 31;
    int tid = threadIdx.x;               // 384 threads
    int e = tid >> 7, j = tid & 127;
    if (blk == 0 && tid < BB) g_ssq[tid] = 0.f;
    // zero out_w accumulator: 8192 float4 over 256 blocks x 32 threads
    if (tid < 32) accO4[blk*32 + tid] = make_float4(0.f,0.f,0.f,0.f);

    {
        int i  = h*384 + e*128 + j;
        int gi = b*NPROJ + i;
        float u = P[gi];
        float f0 = fir_state[gi*2 + 0];
        float f1 = fir_state[gi*2 + 1];
        float w0 = sfw[i*3 + 0], w1 = sfw[i*3 + 1], w2 = sfw[i*3 + 2];
        zps[tid] = w2*u + f0*w0 + f1*w1 + sfb[i];
        dout[FIR_OFF + gi*2 + 0] = f1;   // new_fir = [f1, u]
        dout[FIR_OFF + gi*2 + 1] = u;
    }
    __syncthreads();
    if (tid < 128) {
        int d = h*128 + tid;
        float x2 = zps[tid], x1 = zps[128+tid], v = zps[256+tid];
        float x1v = x1 * v;
        float res = 0.f;
        int base = (b*DD + d)*SS;
#pragma unroll
        for (int s = 0; s < SS; s++) {
            float pole = __expf(lp[d*SS + s]);
            float ni = fmaf(pole, iir[base + s], x1v);
            dout[IIR_OFF + base + s] = ni;
            res = fmaf(resid[d*SS + s], ni, res);
        }
        y[b*DD + d] = x2 * (res + Dres[d]*x1v);
    }
}

// ---------------- xnew = accO + bias + residual + ssq; zero accW1/W3 --------
__global__ void reduce_res_kernel(const float4* __restrict__ accO4,
                                  const float4* __restrict__ x4,
                                  const float4* __restrict__ ob4,
                                  float4* __restrict__ xnew4,
                                  float4* __restrict__ accW1_4,
                                  float4* __restrict__ accW3_4) {
    pdl_trigger();
    pdl_wait();
    int gid = blockIdx.x*256 + threadIdx.x;   // 256 blocks x 256 = 65536
    float4 z4 = make_float4(0.f,0.f,0.f,0.f);
    accW1_4[gid] = z4;                        // zero 65536 f4 = 2*32768
    accW3_4[gid] = z4;
    if (gid < 8192) {
        int b = gid >> 10;
        float4 o = ob4[gid & 1023];
        float4 r = x4[gid];
        float4 p = accO4[gid];
        r.x += o.x + p.x; r.y += o.y + p.y; r.z += o.z + p.z; r.w += o.w + p.w;
        xnew4[gid] = r;
        float ss = r.x*r.x + r.y*r.y + r.z*r.z + r.w*r.w;
#pragma unroll
        for (int o2 = 16; o2; o2 >>= 1) ss += __shfl_xor_sync(0xffffffffu, ss, o2);
        if ((threadIdx.x & 31) == 0) atomicAdd(&g_ssq[b], ss);
    }
}

// ---------------- SwiGLU elementwise + zero accW2 ----------------------------
__global__ void glu_kernel(const float4* __restrict__ A4,
                           const float4* __restrict__ C4,
                           float4* __restrict__ g4out,
                           float4* __restrict__ accW2_4) {
    pdl_trigger();
    pdl_wait();
    int gid = blockIdx.x*256 + threadIdx.x;   // 128 blocks x 256 = 32768
    if (gid < 8192) accW2_4[gid] = make_float4(0.f,0.f,0.f,0.f);
    float4 a = A4[gid], c3 = C4[gid];
    float4 r;
    r.x = (a.x / (1.f + __expf(-a.x))) * c3.x;
    r.y = (a.y / (1.f + __expf(-a.y))) * c3.y;
    r.z = (a.z / (1.f + __expf(-a.z))) * c3.z;
    r.w = (a.w / (1.f + __expf(-a.w))) * c3.w;
    g4out[gid] = r;
}

// ---------------- final: x_out = xnew + accW2 --------------------------------
__global__ void final_kernel(const float4* __restrict__ accW2_4,
                             const float4* __restrict__ xnew4,
                             float4* __restrict__ dout4) {
    pdl_trigger();
    pdl_wait();
    int gid = blockIdx.x*256 + threadIdx.x;   // 32 blocks x 256 = 8192
    float4 r = xnew4[gid], p = accW2_4[gid];
    r.x += p.x; r.y += p.y; r.z += p.z; r.w += p.w;
    dout4[gid] = r;
}

// ---------------- host launcher ----------------------------------------------
static void launch_pdl(const void* func, dim3 grid, dim3 block, size_t smem,
                       void** args) {
    cudaLaunchConfig_t cfg = {};
    cfg.gridDim = grid;
    cfg.blockDim = block;
    cfg.dynamicSmemBytes = smem;
    cfg.stream = 0;
    cudaLaunchAttribute attr[1];
    attr[0].id = cudaLaunchAttributeProgrammaticStreamSerialization;
    attr[0].val.programmaticStreamSerializationAllowed = 1;
    cfg.attrs = attr;
    cfg.numAttrs = 1;
    cudaLaunchKernelExC(&cfg, func, args);
}

extern "C" void kernel_launch(void* const* d_in, const int* in_sizes, int n_in,
                              void* d_out, int out_size) {
    (void)in_sizes; (void)n_in; (void)out_size;
    const float* x          = (const float*)d_in[0];
    const float* fir_state  = (const float*)d_in[1];
    const float* iir_state  = (const float*)d_in[2];
    const float* pre_w      = (const float*)d_in[3];
    const float* proj_w     = (const float*)d_in[4];
    const float* sfw        = (const float*)d_in[5];
    const float* sfb        = (const float*)d_in[6];
    const float* Dres       = (const float*)d_in[7];
    const float* resid      = (const float*)d_in[8];
    const float* lp         = (const float*)d_in[9];
    const float* out_w      = (const float*)d_in[10];
    const float* out_b      = (const float*)d_in[11];
    const float* post_w     = (const float*)d_in[12];
    const float* w1         = (const float*)d_in[13];
    const float* w3         = (const float*)d_in[14];
    const float* w2         = (const float*)d_in[15];
    float* out = (float*)d_out;

    float *xn1, *y, *xnew, *g, *aP, *aO, *aW1, *aW3, *aW2;
    cudaGetSymbolAddress((void**)&xn1,  g_xn1);
    cudaGetSymbolAddress((void**)&y,    g_y);
    cudaGetSymbolAddress((void**)&xnew, g_xnew);
    cudaGetSymbolAddress((void**)&g,    g_g);
    cudaGetSymbolAddress((void**)&aP,   g_accP);
    cudaGetSymbolAddress((void**)&aO,   g_accO);
    cudaGetSymbolAddress((void**)&aW1,  g_accW1);
    cudaGetSymbolAddress((void**)&aW3,  g_accW3);
    cudaGetSymbolAddress((void**)&aW2,  g_accW2);

    const int smem256 = 8*256*8 + 65536;   // 81920
    const int smem64  = 8*64*8  + 65536;   // 69632
    const int smem512 = 8*512*8 + 65536;   // 98304
    cudaFuncSetAttribute(gemv_partial<256>,
                         cudaFuncAttributeMaxDynamicSharedMemorySize, smem256);
    cudaFuncSetAttribute(gemv_partial<64>,
                         cudaFuncAttributeMaxDynamicSharedMemorySize, smem64);
    cudaFuncSetAttribute(gemv_dual<512>,
                         cudaFuncAttributeMaxDynamicSharedMemorySize, smem512);

    int K1 = DD, N1 = NPROJ, N2 = DD, N3 = FFD, K3 = FFD;

    // 1. pre-norm + zero proj accumulator (normal launch; per-replay barrier)
    {
        float4* aP4 = (float4*)aP;
        rmsnorm1_kernel<<<BB, 512>>>(x, pre_w, xn1, aP4);
    }
    // 2. z = xn1 @ proj_w -> accP: 12 col x 16 chunks = 192 blocks
    {
        void* a[] = {&proj_w, &xn1, &aP, &K1, &N1};
        launch_pdl((const void*)gemv_partial<256>, dim3(12,16), dim3(256), smem256, a);
    }
    // 3. FIR + split + IIR -> y, new_fir, new_iir; zero g_ssq + accO
    {
        float4* aO4 = (float4*)aO;
        void* a[] = {&aP, &fir_state, &sfw, &sfb, &iir_state, &lp, &resid, &Dres, &y, &out, &aO4};
        launch_pdl((const void*)fir_iir_kernel, dim3(256), dim3(384), 0, a);
    }
    // 4. y @ out_w -> accO: 4 col x 64 chunks = 256 blocks
    {
        void* a[] = {&out_w, &y, &aO, &K1, &N2};
        launch_pdl((const void*)gemv_partial<64>, dim3(4,64), dim3(256), smem64, a);
    }
    // 5. xnew = accO + out_b + x; ssq; zero accW1/accW3
    {
        const float4 *aO4 = (const float4*)aO, *x4 = (const float4*)x,
                     *o4 = (const float4*)out_b;
        float4 *xn4 = (float4*)xnew, *w14 = (float4*)aW1, *w34 = (float4*)aW3;
        void* a[] = {&aO4, &x4, &o4, &xn4, &w14, &w34};
        launch_pdl((const void*)reduce_res_kernel, dim3(256), dim3(256), 0, a);
    }
    // 6. fused MLP up with post-norm -> accW1/accW3: 16 col x 8 x 2 = 256 blocks
    {
        void* a[] = {&w1, &w3, &xnew, &post_w, &aW1, &aW3, &K1, &N3};
        launch_pdl((const void*)gemv_dual<512>, dim3(16,8,2), dim3(256), smem512, a);
    }
    // 7. SwiGLU gate; zero accW2
    {
        const float4 *a4 = (const float4*)aW1, *c4 = (const float4*)aW3;
        float4 *g4 = (float4*)g, *w24 = (float4*)aW2;
        void* a[] = {&a4, &c4, &g4, &w24};
        launch_pdl((const void*)glu_kernel, dim3(128), dim3(256), 0, a);
    }
    // 8. g @ mlp_w2 -> accW2: 4 col x 64 chunks = 256 blocks
    {
        void* a[] = {&w2, &g, &aW2, &K3, &N2};
        launch_pdl((const void*)gemv_partial<256>, dim3(4,64), dim3(256), smem256, a);
    }
    // 9. x_out = xnew + accW2
    {
        const float4 *w24 = (const float4*)aW2, *xn4c = (const float4*)xnew;
        float4* d4 = (float4*)out;
        void* a[] = {&w24, &xn4c, &d4};
        launch_pdl((const void*)final_kernel, dim3(32), dim3(256), 0, a);
    }
}